// round 3
// baseline (speedup 1.0000x reference)
#include <cuda_runtime.h>
#include <math.h>

// ---------------------------------------------------------------------------
// RDAB block: x[16,64,128,128] fp32
// Round 3: FFMA2 conv with fixed occupancy:
//   - COP=4 (32 acc regs), launch_bounds(128,6)
//   - dual shifted smem copies -> every f32x2 pair is one aligned LDS.64
// ---------------------------------------------------------------------------

#define B_   16
#define C_   64
#define H_   128
#define W_   128
#define HW_  (H_*W_)
#define CHW_ (C_*HW_)

typedef unsigned long long u64;

__device__ float g_buf1[(size_t)B_*CHW_];
__device__ float g_buf2[(size_t)B_*CHW_];
__device__ float g_gate[(size_t)B_*HW_];
__device__ float g_kern1[B_*C_*9];
__device__ float g_kern2[B_*C_*9];

__device__ __forceinline__ float leaky01(float v) {
    return v > 0.f ? v : 0.1f * v;
}

__device__ __forceinline__ u64 pk2(float lo, float hi) {
    u64 r; asm("mov.b64 %0, {%1,%2};" : "=l"(r) : "f"(lo), "f"(hi)); return r;
}
__device__ __forceinline__ void fma2(u64& d, u64 a, u64 b) {
    asm("fma.rn.f32x2 %0, %1, %2, %0;" : "+l"(d) : "l"(a), "l"(b));
}
__device__ __forceinline__ float2 unpk(u64 a) {
    float2 v; asm("mov.b64 {%0,%1}, %2;" : "=f"(v.x), "=f"(v.y) : "l"(a)); return v;
}

// ---------------------------------------------------------------------------
// 1) dynamic-kernel MLP
// ---------------------------------------------------------------------------
__global__ void mlp_kernel(const float* __restrict__ d,
                           const float* __restrict__ k1a, const float* __restrict__ k2a,
                           const float* __restrict__ k1b, const float* __restrict__ k2b,
                           float* __restrict__ kern1, float* __restrict__ kern2)
{
    int b = blockIdx.x;
    int stage = blockIdx.y;
    const float* k1 = stage ? k1b : k1a;
    const float* k2 = stage ? k2b : k2a;
    float* ko = stage ? kern2 : kern1;

    __shared__ float dd[64];
    __shared__ float hid[64];
    int t = threadIdx.x;
    dd[t] = d[b*64 + t];
    __syncthreads();
    float s = 0.f;
#pragma unroll 8
    for (int i = 0; i < 64; i++) s += dd[i] * k1[i*64 + t];
    hid[t] = leaky01(s);
    __syncthreads();
#pragma unroll
    for (int r = 0; r < 9; r++) {
        int o = r*64 + t;
        float s2 = 0.f;
#pragma unroll 8
        for (int i = 0; i < 64; i++) s2 += hid[i] * k2[i*576 + o];
        ko[b*576 + o] = s2;
    }
}

// ---------------------------------------------------------------------------
// 2) gating map
// ---------------------------------------------------------------------------
__global__ void gate_kernel(const float* __restrict__ in,
                            const float* __restrict__ cw,
                            const float* __restrict__ cb,
                            float* __restrict__ M)
{
    __shared__ float scw[C_];
    if (threadIdx.x < C_) scw[threadIdx.x] = cw[threadIdx.x];
    __syncthreads();
    int idx = blockIdx.x * blockDim.x + threadIdx.x;
    int b  = idx / HW_;
    int hw = idx - b * HW_;
    const float* p = in + (size_t)b * CHW_ + hw;
    float s = cb[0];
#pragma unroll 8
    for (int c = 0; c < C_; c++) s += scw[c] * p[(size_t)c * HW_];
    M[idx] = 1.f / (1.f + expf(-s));
}

// ---------------------------------------------------------------------------
// 3) fused RDA
// ---------------------------------------------------------------------------
__global__ void rda_kernel(const float* __restrict__ in,
                           const float* __restrict__ kern,
                           const float* __restrict__ M,
                           float* __restrict__ out)
{
    int idx = blockIdx.x * blockDim.x + threadIdx.x;
    int c = blockIdx.y;
    int b = blockIdx.z;
    int h = idx >> 7;
    int w = idx & 127;

    const float* k = kern + (b*C_ + c) * 9;
    float k0 = k[0], k1 = k[1], k2 = k[2],
          k3 = k[3], k4 = k[4], k5 = k[5],
          k6 = k[6], k7 = k[7], k8 = k[8];

    const float* p = in + ((size_t)b*C_ + c) * HW_;
    float dw = 0.f;
    if (h > 0) {
        const float* r = p + (h-1)*W_;
        if (w > 0)    dw += k0 * r[w-1];
                      dw += k1 * r[w];
        if (w < 127)  dw += k2 * r[w+1];
    }
    {
        const float* r = p + h*W_;
        if (w > 0)    dw += k3 * r[w-1];
                      dw += k4 * r[w];
        if (w < 127)  dw += k5 * r[w+1];
    }
    if (h < 127) {
        const float* r = p + (h+1)*W_;
        if (w > 0)    dw += k6 * r[w-1];
                      dw += k7 * r[w];
        if (w < 127)  dw += k8 * r[w+1];
    }
    float v = leaky01(dw);
    float m = M[(size_t)b*HW_ + idx];
    v = v * m + p[h*W_ + w];
    out[((size_t)b*C_ + c) * HW_ + idx] = leaky01(v);
}

// ---------------------------------------------------------------------------
// 4) dense 3x3 conv 64->64, FFMA2, COP=4.
//    Block 128 thr: tw = tid&15 (8 px each), th = tid>>4 (8 rows).
//    Smem rows kept twice: sA[j]=v(j), sB[j]=v(j+1) -> any pair is 1 LDS.64.
//    grid = (16 h-tiles, 16 oc-groups, 16 batches)
// ---------------------------------------------------------------------------
#define COP 4

__global__ void __launch_bounds__(128, 6)
conv3x3_f32x2(const float* __restrict__ in,
              const float* __restrict__ wgt,
              const float* __restrict__ bias,
              const float* __restrict__ residual,
              float* __restrict__ out,
              int apply_leaky)
{
    __shared__ float sA[10][132];        // v at col j (j=w+1), j=0..129
    __shared__ float sB[10][132];        // sB[j] = v(j+1),     j=0..128
    __shared__ u64   sW2[C_ * COP * 9];  // {q,q} pairs, 18432 B

    int b   = blockIdx.z;
    int co0 = blockIdx.y * COP;
    int h0  = blockIdx.x * 8;
    int tid = threadIdx.x;
    int tw  = tid & 15;                  // pixel block 8*tw
    int th  = tid >> 4;                  // output row h0+th
    int j0  = 8 * tw;

    for (int i = tid; i < C_ * COP * 9; i += 128) {
        int ci  = i / (COP*9);
        int rem = i - ci * (COP*9);
        int oc  = rem / 9;
        int tap = rem - oc * 9;
        float q = wgt[((co0 + oc) * C_ + ci) * 9 + tap];
        sW2[i] = pk2(q, q);
    }

    u64 acc[COP][4];
#pragma unroll
    for (int oc = 0; oc < COP; oc++)
#pragma unroll
        for (int m = 0; m < 4; m++) acc[oc][m] = 0ull;

    const float* inb = in + (size_t)b * CHW_;

    for (int ci = 0; ci < C_; ci++) {
        __syncthreads();
        const float* cp = inb + (size_t)ci * HW_;
#pragma unroll
        for (int r = 0; r < 10; r++) {
            int gy = h0 - 1 + r;
            bool rowok = (gy >= 0) && (gy < H_);
            int w = tid - 1;                       // j = tid
            float v = (rowok && w >= 0) ? cp[gy * W_ + w] : 0.f;
            sA[r][tid] = v;
            if (tid >= 1) sB[r][tid - 1] = v;
            if (tid < 2) {                         // j = 128,129
                int w2 = 127 + tid;
                float v2 = (rowok && w2 < W_) ? cp[gy * W_ + w2] : 0.f;
                sA[r][128 + tid] = v2;
                sB[r][127 + tid] = v2;
            }
        }
        __syncthreads();

        const u64* wci = &sW2[ci * (COP * 9)];
#pragma unroll
        for (int r = 0; r < 3; r++) {
            const float* pa = &sA[th + r][j0];
            const float* pb = &sB[th + r][j0];
            u64 P[9];
            P[0] = *(const u64*)(pa    );  // (v0,v1)
            P[1] = *(const u64*)(pb    );  // (v1,v2)
            P[2] = *(const u64*)(pa + 2);
            P[3] = *(const u64*)(pb + 2);
            P[4] = *(const u64*)(pa + 4);
            P[5] = *(const u64*)(pb + 4);
            P[6] = *(const u64*)(pa + 6);
            P[7] = *(const u64*)(pb + 6);
            P[8] = *(const u64*)(pa + 8);
#pragma unroll
            for (int oc = 0; oc < COP; oc++) {
                const u64* wr = wci + oc * 9 + r * 3;
                u64 w0 = wr[0], w1 = wr[1], w2 = wr[2];
#pragma unroll
                for (int m = 0; m < 4; m++) {
                    fma2(acc[oc][m], P[2*m    ], w0);
                    fma2(acc[oc][m], P[2*m + 1], w1);
                    fma2(acc[oc][m], P[2*m + 2], w2);
                }
            }
        }
    }

#pragma unroll
    for (int oc = 0; oc < COP; oc++) {
        float bv = bias[co0 + oc];
        size_t base = (((size_t)b * C_ + co0 + oc) * H_ + (h0 + th)) * W_ + j0;
#pragma unroll
        for (int m = 0; m < 4; m++) {
            float2 v = unpk(acc[oc][m]);
            v.x += bv; v.y += bv;
            if (apply_leaky) { v.x = leaky01(v.x); v.y = leaky01(v.y); }
            if (residual) {
                v.x += residual[base + 2*m];
                v.y += residual[base + 2*m + 1];
            }
            *(float2*)&out[base + 2*m] = v;
        }
    }
}

// ---------------------------------------------------------------------------
// launch
// ---------------------------------------------------------------------------
extern "C" void kernel_launch(void* const* d_in, const int* in_sizes, int n_in,
                              void* d_out, int out_size)
{
    const float* x       = (const float*)d_in[0];
    const float* d       = (const float*)d_in[1];
    const float* da1_k1  = (const float*)d_in[2];
    const float* da1_k2  = (const float*)d_in[3];
    const float* da1_cw  = (const float*)d_in[4];
    const float* da1_cb  = (const float*)d_in[5];
    const float* da2_k1  = (const float*)d_in[6];
    const float* da2_k2  = (const float*)d_in[7];
    const float* da2_cw  = (const float*)d_in[8];
    const float* da2_cb  = (const float*)d_in[9];
    const float* conv1_w = (const float*)d_in[10];
    const float* conv1_b = (const float*)d_in[11];
    const float* conv2_w = (const float*)d_in[12];
    const float* conv2_b = (const float*)d_in[13];
    float* out = (float*)d_out;

    float *buf1, *buf2, *gate, *kern1, *kern2;
    cudaGetSymbolAddress((void**)&buf1,  g_buf1);
    cudaGetSymbolAddress((void**)&buf2,  g_buf2);
    cudaGetSymbolAddress((void**)&gate,  g_gate);
    cudaGetSymbolAddress((void**)&kern1, g_kern1);
    cudaGetSymbolAddress((void**)&kern2, g_kern2);

    mlp_kernel<<<dim3(B_, 2), 64>>>(d, da1_k1, da1_k2, da2_k1, da2_k2, kern1, kern2);

    gate_kernel<<<(B_*HW_)/256, 256>>>(x, da1_cw, da1_cb, gate);
    rda_kernel<<<dim3(HW_/256, C_, B_), 256>>>(x, kern1, gate, buf1);

    conv3x3_f32x2<<<dim3(16, C_/COP, B_), 128>>>(buf1, conv1_w, conv1_b, nullptr, buf2, 1);

    gate_kernel<<<(B_*HW_)/256, 256>>>(buf2, da2_cw, da2_cb, gate);
    rda_kernel<<<dim3(HW_/256, C_, B_), 256>>>(buf2, kern2, gate, buf1);

    conv3x3_f32x2<<<dim3(16, C_/COP, B_), 128>>>(buf1, conv2_w, conv2_b, x, out, 0);
}

// round 5
// speedup vs baseline: 2.0766x; 2.0766x over previous
#include <cuda_runtime.h>
#include <math.h>

// ---------------------------------------------------------------------------
// RDAB block: x[16,64,128,128] fp32
// Round 5: FFMA2 conv (R4 design) with alignment fixed:
//   - halo shift = 4 floats -> cp.async 16B dsts are 16B-aligned
//   - __align__(16) staging buffer -> LDS.64 legal
//   - strided pixel-pair mapping -> conflict-free LDS.64
//   - cp.async double-buffered input staging -> L2 latency hidden
// ---------------------------------------------------------------------------

#define B_   16
#define C_   64
#define H_   128
#define W_   128
#define HW_  (H_*W_)
#define CHW_ (C_*HW_)

typedef unsigned long long u64;
typedef unsigned int u32;

__device__ float g_buf1[(size_t)B_*CHW_];
__device__ float g_buf2[(size_t)B_*CHW_];
__device__ float g_gate[(size_t)B_*HW_];
__device__ float g_kern1[B_*C_*9];
__device__ float g_kern2[B_*C_*9];

__device__ __forceinline__ float leaky01(float v) {
    return v > 0.f ? v : 0.1f * v;
}
__device__ __forceinline__ u64 pk2(float lo, float hi) {
    u64 r; asm("mov.b64 %0, {%1,%2};" : "=l"(r) : "f"(lo), "f"(hi)); return r;
}
__device__ __forceinline__ void fma2(u64& d, u64 a, u64 b) {
    asm("fma.rn.f32x2 %0, %1, %2, %0;" : "+l"(d) : "l"(a), "l"(b));
}
__device__ __forceinline__ float2 unpk(u64 a) {
    float2 v; asm("mov.b64 {%0,%1}, %2;" : "=f"(v.x), "=f"(v.y) : "l"(a)); return v;
}
__device__ __forceinline__ u32 smem_u32(const void* p) {
    u32 a;
    asm("{ .reg .u64 t; cvta.to.shared.u64 t, %1; cvt.u32.u64 %0, t; }"
        : "=r"(a) : "l"(p));
    return a;
}
__device__ __forceinline__ void cp_async16(u32 dst, const void* src) {
    asm volatile("cp.async.ca.shared.global [%0], [%1], 16;\n"
                 :: "r"(dst), "l"(src));
}
__device__ __forceinline__ void cp_commit() {
    asm volatile("cp.async.commit_group;\n");
}
__device__ __forceinline__ void cp_wait_all() {
    asm volatile("cp.async.wait_group 0;\n");
}

// ---------------------------------------------------------------------------
// 1) dynamic-kernel MLP
// ---------------------------------------------------------------------------
__global__ void mlp_kernel(const float* __restrict__ d,
                           const float* __restrict__ k1a, const float* __restrict__ k2a,
                           const float* __restrict__ k1b, const float* __restrict__ k2b,
                           float* __restrict__ kern1, float* __restrict__ kern2)
{
    int b = blockIdx.x;
    int stage = blockIdx.y;
    const float* k1 = stage ? k1b : k1a;
    const float* k2 = stage ? k2b : k2a;
    float* ko = stage ? kern2 : kern1;

    __shared__ float dd[64];
    __shared__ float hid[64];
    int t = threadIdx.x;
    dd[t] = d[b*64 + t];
    __syncthreads();
    float s = 0.f;
#pragma unroll 8
    for (int i = 0; i < 64; i++) s += dd[i] * k1[i*64 + t];
    hid[t] = leaky01(s);
    __syncthreads();
#pragma unroll
    for (int r = 0; r < 9; r++) {
        int o = r*64 + t;
        float s2 = 0.f;
#pragma unroll 8
        for (int i = 0; i < 64; i++) s2 += hid[i] * k2[i*576 + o];
        ko[b*576 + o] = s2;
    }
}

// ---------------------------------------------------------------------------
// 2) gating map
// ---------------------------------------------------------------------------
__global__ void gate_kernel(const float* __restrict__ in,
                            const float* __restrict__ cw,
                            const float* __restrict__ cb,
                            float* __restrict__ M)
{
    __shared__ float scw[C_];
    if (threadIdx.x < C_) scw[threadIdx.x] = cw[threadIdx.x];
    __syncthreads();
    int idx = blockIdx.x * blockDim.x + threadIdx.x;
    int b  = idx / HW_;
    int hw = idx - b * HW_;
    const float* p = in + (size_t)b * CHW_ + hw;
    float s = cb[0];
#pragma unroll 8
    for (int c = 0; c < C_; c++) s += scw[c] * p[(size_t)c * HW_];
    M[idx] = 1.f / (1.f + expf(-s));
}

// ---------------------------------------------------------------------------
// 3) fused RDA
// ---------------------------------------------------------------------------
__global__ void rda_kernel(const float* __restrict__ in,
                           const float* __restrict__ kern,
                           const float* __restrict__ M,
                           float* __restrict__ out)
{
    int idx = blockIdx.x * blockDim.x + threadIdx.x;
    int c = blockIdx.y;
    int b = blockIdx.z;
    int h = idx >> 7;
    int w = idx & 127;

    const float* k = kern + (b*C_ + c) * 9;
    float k0 = k[0], k1 = k[1], k2 = k[2],
          k3 = k[3], k4 = k[4], k5 = k[5],
          k6 = k[6], k7 = k[7], k8 = k[8];

    const float* p = in + ((size_t)b*C_ + c) * HW_;
    float dw = 0.f;
    if (h > 0) {
        const float* r = p + (h-1)*W_;
        if (w > 0)    dw += k0 * r[w-1];
                      dw += k1 * r[w];
        if (w < 127)  dw += k2 * r[w+1];
    }
    {
        const float* r = p + h*W_;
        if (w > 0)    dw += k3 * r[w-1];
                      dw += k4 * r[w];
        if (w < 127)  dw += k5 * r[w+1];
    }
    if (h < 127) {
        const float* r = p + (h+1)*W_;
        if (w > 0)    dw += k6 * r[w-1];
                      dw += k7 * r[w];
        if (w < 127)  dw += k8 * r[w+1];
    }
    float v = leaky01(dw);
    float m = M[(size_t)b*HW_ + idx];
    v = v * m + p[h*W_ + w];
    out[((size_t)b*C_ + c) * HW_ + idx] = leaky01(v);
}

// ---------------------------------------------------------------------------
// 4) dense 3x3 conv 64->64, FFMA2, conflict-free, cp.async double-buffered.
//    Block 128: th = tid>>4 (8 output rows), tw = tid&15.
//    Thread pixels: pairs at w = 2*tw + 32*m, m=0..3; COP=4 oc.
//    Smem row layout: sIn[r][j] = v(w = j-4), j=4..131; halo j=3 / j=132.
//      pair (v_w,v_{w+1}) = u64 @ j=w+4 (even, 8B aligned, conflict-free).
//      cp.async dst j = 4+4*seg -> byte offset multiple of 16.
//    grid = (16 h-tiles, 16 oc-groups, 16 batches)
// ---------------------------------------------------------------------------
#define COP 4
#define RW  136      // padded row width (floats); 544B = 34*16B

__global__ void __launch_bounds__(128, 5)
conv3x3_f32x2(const float* __restrict__ in,
              const float* __restrict__ wgt,
              const float* __restrict__ bias,
              const float* __restrict__ residual,
              float* __restrict__ out,
              int apply_leaky)
{
    __shared__ __align__(16) float sIn[2][10][RW];   // 10.9 KB
    __shared__ u64 sW2[C_ * COP * 9];                // 18.4 KB, {q,q} pairs

    int b   = blockIdx.z;
    int co0 = blockIdx.y * COP;
    int h0  = blockIdx.x * 8;
    int tid = threadIdx.x;
    int tw  = tid & 15;
    int th  = tid >> 4;

    // zero both buffers once (covers halo cols + out-of-image rows forever)
    for (int i = tid; i < 2 * 10 * RW; i += 128)
        ((float*)sIn)[i] = 0.f;

    // stage duplicated weights
    for (int i = tid; i < C_ * COP * 9; i += 128) {
        int ci  = i / 36;
        int rem = i - ci * 36;
        int oc  = rem / 9;
        int tap = rem - oc * 9;
        float q = wgt[((co0 + oc) * C_ + ci) * 9 + tap];
        sW2[i] = pk2(q, q);
    }

    const float* inb = in + (size_t)b * CHW_;
    u32 sbase[2] = { smem_u32(&sIn[0][0][0]), smem_u32(&sIn[1][0][0]) };

    __syncthreads();   // zero-fill visible before first cp.async

    // prefetch: ci's 10 rows as 16B chunks; idx = r*32+seg, dst j = 4+seg*4
    auto prefetch = [&](int ci, int buf) {
        const float* cp = inb + (size_t)ci * HW_;
#pragma unroll
        for (int k = 0; k < 3; k++) {
            int idx = tid + k * 128;
            if (idx < 320) {
                int r   = idx >> 5;
                int seg = idx & 31;
                int gy  = h0 - 1 + r;
                if (gy >= 0 && gy < H_) {
                    u32 dst = sbase[buf] + (u32)((r * RW + 4 + seg * 4) * 4);
                    cp_async16(dst, cp + gy * W_ + seg * 4);
                }
            }
        }
    };

    u64 acc[COP][4];
#pragma unroll
    for (int oc = 0; oc < COP; oc++)
#pragma unroll
        for (int m = 0; m < 4; m++) acc[oc][m] = 0ull;

    prefetch(0, 0);
    cp_commit();

    for (int ci = 0; ci < C_; ci++) {
        cp_wait_all();
        __syncthreads();                 // buf[ci&1] ready for everyone

        if (ci < C_ - 1) {
            prefetch(ci + 1, (ci + 1) & 1);
            cp_commit();
        }

        const float* bufp = &sIn[ci & 1][0][0];
        const u64*   wci  = &sW2[ci * 36];

#pragma unroll
        for (int r = 0; r < 3; r++) {
            const float* rowp = bufp + (th + r) * RW;
            u64 Pl[4], Pm[4], Pr[4];
#pragma unroll
            for (int m = 0; m < 4; m++) {
                int jm = 2 * tw + 32 * m + 4;
                u64 pm = *(const u64*)(rowp + jm);     // (v_w, v_{w+1})
                float2 mid = unpk(pm);
                float vL = rowp[jm - 1];               // v_{w-1}
                float vR = rowp[jm + 2];               // v_{w+2}
                Pm[m] = pm;
                Pl[m] = pk2(vL, mid.x);
                Pr[m] = pk2(mid.y, vR);
            }
#pragma unroll
            for (int oc = 0; oc < COP; oc++) {
                const u64* wr = wci + oc * 9 + r * 3;
                u64 w0 = wr[0], w1 = wr[1], w2 = wr[2];
#pragma unroll
                for (int m = 0; m < 4; m++) {
                    fma2(acc[oc][m], Pl[m], w0);
                    fma2(acc[oc][m], Pm[m], w1);
                    fma2(acc[oc][m], Pr[m], w2);
                }
            }
        }
        __syncthreads();                 // done reading buf[ci&1]
    }

    // epilogue
#pragma unroll
    for (int oc = 0; oc < COP; oc++) {
        float bv = bias[co0 + oc];
        size_t rowbase = (((size_t)b * C_ + co0 + oc) * H_ + (h0 + th)) * W_;
#pragma unroll
        for (int m = 0; m < 4; m++) {
            int w = 2 * tw + 32 * m;
            float2 v = unpk(acc[oc][m]);
            v.x += bv; v.y += bv;
            if (apply_leaky) { v.x = leaky01(v.x); v.y = leaky01(v.y); }
            if (residual) {
                const float2 rv = *(const float2*)&residual[rowbase + w];
                v.x += rv.x; v.y += rv.y;
            }
            *(float2*)&out[rowbase + w] = v;
        }
    }
}

// ---------------------------------------------------------------------------
// launch
// ---------------------------------------------------------------------------
extern "C" void kernel_launch(void* const* d_in, const int* in_sizes, int n_in,
                              void* d_out, int out_size)
{
    const float* x       = (const float*)d_in[0];
    const float* d       = (const float*)d_in[1];
    const float* da1_k1  = (const float*)d_in[2];
    const float* da1_k2  = (const float*)d_in[3];
    const float* da1_cw  = (const float*)d_in[4];
    const float* da1_cb  = (const float*)d_in[5];
    const float* da2_k1  = (const float*)d_in[6];
    const float* da2_k2  = (const float*)d_in[7];
    const float* da2_cw  = (const float*)d_in[8];
    const float* da2_cb  = (const float*)d_in[9];
    const float* conv1_w = (const float*)d_in[10];
    const float* conv1_b = (const float*)d_in[11];
    const float* conv2_w = (const float*)d_in[12];
    const float* conv2_b = (const float*)d_in[13];
    float* out = (float*)d_out;

    float *buf1, *buf2, *gate, *kern1, *kern2;
    cudaGetSymbolAddress((void**)&buf1,  g_buf1);
    cudaGetSymbolAddress((void**)&buf2,  g_buf2);
    cudaGetSymbolAddress((void**)&gate,  g_gate);
    cudaGetSymbolAddress((void**)&kern1, g_kern1);
    cudaGetSymbolAddress((void**)&kern2, g_kern2);

    mlp_kernel<<<dim3(B_, 2), 64>>>(d, da1_k1, da1_k2, da2_k1, da2_k2, kern1, kern2);

    gate_kernel<<<(B_*HW_)/256, 256>>>(x, da1_cw, da1_cb, gate);
    rda_kernel<<<dim3(HW_/256, C_, B_), 256>>>(x, kern1, gate, buf1);

    conv3x3_f32x2<<<dim3(16, C_/COP, B_), 128>>>(buf1, conv1_w, conv1_b, nullptr, buf2, 1);

    gate_kernel<<<(B_*HW_)/256, 256>>>(buf2, da2_cw, da2_cb, gate);
    rda_kernel<<<dim3(HW_/256, C_, B_), 256>>>(buf2, kern2, gate, buf1);

    conv3x3_f32x2<<<dim3(16, C_/COP, B_), 128>>>(buf1, conv2_w, conv2_b, x, out, 0);
}

// round 6
// speedup vs baseline: 2.4627x; 1.1859x over previous
#include <cuda_runtime.h>
#include <math.h>

// ---------------------------------------------------------------------------
// RDAB block: x[16,64,128,128] fp32
// Round 6: FFMA2 conv, overhead-reduction edition:
//   - 2 output rows per thread -> input rows + weights amortized
//   - packed weight loads (LDS.128 x4 + LDS.64 per (ci,oc))
//   - strided conflict-free pairs + cp.async double buffering (from R5)
// ---------------------------------------------------------------------------

#define B_   16
#define C_   64
#define H_   128
#define W_   128
#define HW_  (H_*W_)
#define CHW_ (C_*HW_)

typedef unsigned long long u64;
typedef unsigned int u32;

__device__ float g_buf1[(size_t)B_*CHW_];
__device__ float g_buf2[(size_t)B_*CHW_];
__device__ float g_gate[(size_t)B_*HW_];
__device__ float g_kern1[B_*C_*9];
__device__ float g_kern2[B_*C_*9];

__device__ __forceinline__ float leaky01(float v) {
    return v > 0.f ? v : 0.1f * v;
}
__device__ __forceinline__ u64 pk2(float lo, float hi) {
    u64 r; asm("mov.b64 %0, {%1,%2};" : "=l"(r) : "f"(lo), "f"(hi)); return r;
}
__device__ __forceinline__ void fma2(u64& d, u64 a, u64 b) {
    asm("fma.rn.f32x2 %0, %1, %2, %0;" : "+l"(d) : "l"(a), "l"(b));
}
__device__ __forceinline__ float2 unpk(u64 a) {
    float2 v; asm("mov.b64 {%0,%1}, %2;" : "=f"(v.x), "=f"(v.y) : "l"(a)); return v;
}
__device__ __forceinline__ u32 smem_u32(const void* p) {
    u32 a;
    asm("{ .reg .u64 t; cvta.to.shared.u64 t, %1; cvt.u32.u64 %0, t; }"
        : "=r"(a) : "l"(p));
    return a;
}
__device__ __forceinline__ void cp_async16(u32 dst, const void* src) {
    asm volatile("cp.async.ca.shared.global [%0], [%1], 16;\n"
                 :: "r"(dst), "l"(src));
}
__device__ __forceinline__ void cp_commit() {
    asm volatile("cp.async.commit_group;\n");
}
__device__ __forceinline__ void cp_wait_all() {
    asm volatile("cp.async.wait_group 0;\n");
}

// ---------------------------------------------------------------------------
// 1) dynamic-kernel MLP
// ---------------------------------------------------------------------------
__global__ void mlp_kernel(const float* __restrict__ d,
                           const float* __restrict__ k1a, const float* __restrict__ k2a,
                           const float* __restrict__ k1b, const float* __restrict__ k2b,
                           float* __restrict__ kern1, float* __restrict__ kern2)
{
    int b = blockIdx.x;
    int stage = blockIdx.y;
    const float* k1 = stage ? k1b : k1a;
    const float* k2 = stage ? k2b : k2a;
    float* ko = stage ? kern2 : kern1;

    __shared__ float dd[64];
    __shared__ float hid[64];
    int t = threadIdx.x;
    dd[t] = d[b*64 + t];
    __syncthreads();
    float s = 0.f;
#pragma unroll 8
    for (int i = 0; i < 64; i++) s += dd[i] * k1[i*64 + t];
    hid[t] = leaky01(s);
    __syncthreads();
#pragma unroll
    for (int r = 0; r < 9; r++) {
        int o = r*64 + t;
        float s2 = 0.f;
#pragma unroll 8
        for (int i = 0; i < 64; i++) s2 += hid[i] * k2[i*576 + o];
        ko[b*576 + o] = s2;
    }
}

// ---------------------------------------------------------------------------
// 2) gating map
// ---------------------------------------------------------------------------
__global__ void gate_kernel(const float* __restrict__ in,
                            const float* __restrict__ cw,
                            const float* __restrict__ cb,
                            float* __restrict__ M)
{
    __shared__ float scw[C_];
    if (threadIdx.x < C_) scw[threadIdx.x] = cw[threadIdx.x];
    __syncthreads();
    int idx = blockIdx.x * blockDim.x + threadIdx.x;
    int b  = idx / HW_;
    int hw = idx - b * HW_;
    const float* p = in + (size_t)b * CHW_ + hw;
    float s = cb[0];
#pragma unroll 8
    for (int c = 0; c < C_; c++) s += scw[c] * p[(size_t)c * HW_];
    M[idx] = 1.f / (1.f + expf(-s));
}

// ---------------------------------------------------------------------------
// 3) fused RDA
// ---------------------------------------------------------------------------
__global__ void rda_kernel(const float* __restrict__ in,
                           const float* __restrict__ kern,
                           const float* __restrict__ M,
                           float* __restrict__ out)
{
    int idx = blockIdx.x * blockDim.x + threadIdx.x;
    int c = blockIdx.y;
    int b = blockIdx.z;
    int h = idx >> 7;
    int w = idx & 127;

    const float* k = kern + (b*C_ + c) * 9;
    float k0 = k[0], k1 = k[1], k2 = k[2],
          k3 = k[3], k4 = k[4], k5 = k[5],
          k6 = k[6], k7 = k[7], k8 = k[8];

    const float* p = in + ((size_t)b*C_ + c) * HW_;
    float dw = 0.f;
    if (h > 0) {
        const float* r = p + (h-1)*W_;
        if (w > 0)    dw += k0 * r[w-1];
                      dw += k1 * r[w];
        if (w < 127)  dw += k2 * r[w+1];
    }
    {
        const float* r = p + h*W_;
        if (w > 0)    dw += k3 * r[w-1];
                      dw += k4 * r[w];
        if (w < 127)  dw += k5 * r[w+1];
    }
    if (h < 127) {
        const float* r = p + (h+1)*W_;
        if (w > 0)    dw += k6 * r[w-1];
                      dw += k7 * r[w];
        if (w < 127)  dw += k8 * r[w+1];
    }
    float v = leaky01(dw);
    float m = M[(size_t)b*HW_ + idx];
    v = v * m + p[h*W_ + w];
    out[((size_t)b*C_ + c) * HW_ + idx] = leaky01(v);
}

// ---------------------------------------------------------------------------
// 4) dense 3x3 conv 64->64, FFMA2, 2-rows-per-thread.
//    Block 128: lane = tid&31 (pairs at w = 2*lane + 64*m, m=0..1),
//               th = tid>>5 (output rows 2*th, 2*th+1). Tile: 8 rows x 128 w.
//    Staging rows s=0..9 <-> global h0-1+s; output local row o' uses s=o',o'+1,o'+2.
//    Thread holds P (Pl/Pm/Pr) for staging rows 2th..2th+3 (24 u64).
//    Weights packed: sW2[(ci*COP+oc)*10 + tap] ({q,q}), 16B-aligned stride.
//    grid = (16 h-tiles, 16 oc-groups, 16 batches)
// ---------------------------------------------------------------------------
#define COP 4
#define RW  136      // padded row width (floats); 544B = 34*16B

__global__ void __launch_bounds__(128, 4)
conv3x3_f32x2(const float* __restrict__ in,
              const float* __restrict__ wgt,
              const float* __restrict__ bias,
              const float* __restrict__ residual,
              float* __restrict__ out,
              int apply_leaky)
{
    __shared__ __align__(16) float sIn[2][10][RW];   // 10.9 KB
    __shared__ __align__(16) u64 sW2[C_ * COP * 10]; // 20.5 KB (stride-10 pad)

    int b    = blockIdx.z;
    int co0  = blockIdx.y * COP;
    int h0   = blockIdx.x * 8;
    int tid  = threadIdx.x;
    int lane = tid & 31;
    int th   = tid >> 5;                 // 0..3 -> output rows 2th, 2th+1

    // zero staging buffers once (halo cols + out-of-image rows stay 0)
    for (int i = tid; i < 2 * 10 * RW; i += 128)
        ((float*)sIn)[i] = 0.f;

    // stage packed duplicated weights
    for (int i = tid; i < C_ * COP * 9; i += 128) {
        int ci  = i / 36;
        int rem = i - ci * 36;
        int oc  = rem / 9;
        int tap = rem - oc * 9;
        float q = wgt[((co0 + oc) * C_ + ci) * 9 + tap];
        sW2[(ci * COP + oc) * 10 + tap] = pk2(q, q);
    }

    const float* inb = in + (size_t)b * CHW_;
    u32 sbase[2] = { smem_u32(&sIn[0][0][0]), smem_u32(&sIn[1][0][0]) };

    __syncthreads();   // zero-fill + weights visible

    // prefetch ci's 10 rows as 16B chunks; idx = r*32+seg, dst j = 4+seg*4
    auto prefetch = [&](int ci, int buf) {
        const float* cp = inb + (size_t)ci * HW_;
#pragma unroll
        for (int k = 0; k < 3; k++) {
            int idx = tid + k * 128;
            if (idx < 320) {
                int r   = idx >> 5;
                int seg = idx & 31;
                int gy  = h0 - 1 + r;
                if (gy >= 0 && gy < H_) {
                    u32 dst = sbase[buf] + (u32)((r * RW + 4 + seg * 4) * 4);
                    cp_async16(dst, cp + gy * W_ + seg * 4);
                }
            }
        }
    };

    u64 acc[COP][2][2];
#pragma unroll
    for (int oc = 0; oc < COP; oc++)
#pragma unroll
        for (int o = 0; o < 2; o++)
#pragma unroll
            for (int m = 0; m < 2; m++) acc[oc][o][m] = 0ull;

    prefetch(0, 0);
    cp_commit();

    for (int ci = 0; ci < C_; ci++) {
        cp_wait_all();
        __syncthreads();                 // buf[ci&1] ready

        if (ci < C_ - 1) {
            prefetch(ci + 1, (ci + 1) & 1);
            cp_commit();
        }

        const float* bufp = &sIn[ci & 1][0][0];

        // load P for 4 staging rows: s = 2*th + k
        u64 Pl[4][2], Pm[4][2], Pr[4][2];
#pragma unroll
        for (int k = 0; k < 4; k++) {
            const float* rowp = bufp + (2 * th + k) * RW;
#pragma unroll
            for (int m = 0; m < 2; m++) {
                int jm = 2 * lane + 64 * m + 4;
                u64 pm = *(const u64*)(rowp + jm);     // (v_w, v_{w+1})
                float2 mid = unpk(pm);
                float vL = rowp[jm - 1];
                float vR = rowp[jm + 2];
                Pm[k][m] = pm;
                Pl[k][m] = pk2(vL, mid.x);
                Pr[k][m] = pk2(mid.y, vR);
            }
        }

#pragma unroll
        for (int oc = 0; oc < COP; oc++) {
            const u64* wp = &sW2[(ci * COP + oc) * 10];
            ulonglong2 q01 = *(const ulonglong2*)(wp);
            ulonglong2 q23 = *(const ulonglong2*)(wp + 2);
            ulonglong2 q45 = *(const ulonglong2*)(wp + 4);
            ulonglong2 q67 = *(const ulonglong2*)(wp + 6);
            u64 W0 = q01.x, W1 = q01.y, W2 = q23.x;
            u64 W3 = q23.y, W4 = q45.x, W5 = q45.y;
            u64 W6 = q67.x, W7 = q67.y, W8 = wp[8];
#pragma unroll
            for (int o = 0; o < 2; o++) {
#pragma unroll
                for (int m = 0; m < 2; m++) {
                    fma2(acc[oc][o][m], Pl[o    ][m], W0);
                    fma2(acc[oc][o][m], Pm[o    ][m], W1);
                    fma2(acc[oc][o][m], Pr[o    ][m], W2);
                    fma2(acc[oc][o][m], Pl[o + 1][m], W3);
                    fma2(acc[oc][o][m], Pm[o + 1][m], W4);
                    fma2(acc[oc][o][m], Pr[o + 1][m], W5);
                    fma2(acc[oc][o][m], Pl[o + 2][m], W6);
                    fma2(acc[oc][o][m], Pm[o + 2][m], W7);
                    fma2(acc[oc][o][m], Pr[o + 2][m], W8);
                }
            }
        }
        __syncthreads();                 // done reading buf[ci&1]
    }

    // epilogue
#pragma unroll
    for (int oc = 0; oc < COP; oc++) {
        float bv = bias[co0 + oc];
#pragma unroll
        for (int o = 0; o < 2; o++) {
            int row = h0 + 2 * th + o;
            size_t rowbase = (((size_t)b * C_ + co0 + oc) * H_ + row) * W_;
#pragma unroll
            for (int m = 0; m < 2; m++) {
                int w = 2 * lane + 64 * m;
                float2 v = unpk(acc[oc][o][m]);
                v.x += bv; v.y += bv;
                if (apply_leaky) { v.x = leaky01(v.x); v.y = leaky01(v.y); }
                if (residual) {
                    const float2 rv = *(const float2*)&residual[rowbase + w];
                    v.x += rv.x; v.y += rv.y;
                }
                *(float2*)&out[rowbase + w] = v;
            }
        }
    }
}

// ---------------------------------------------------------------------------
// launch
// ---------------------------------------------------------------------------
extern "C" void kernel_launch(void* const* d_in, const int* in_sizes, int n_in,
                              void* d_out, int out_size)
{
    const float* x       = (const float*)d_in[0];
    const float* d       = (const float*)d_in[1];
    const float* da1_k1  = (const float*)d_in[2];
    const float* da1_k2  = (const float*)d_in[3];
    const float* da1_cw  = (const float*)d_in[4];
    const float* da1_cb  = (const float*)d_in[5];
    const float* da2_k1  = (const float*)d_in[6];
    const float* da2_k2  = (const float*)d_in[7];
    const float* da2_cw  = (const float*)d_in[8];
    const float* da2_cb  = (const float*)d_in[9];
    const float* conv1_w = (const float*)d_in[10];
    const float* conv1_b = (const float*)d_in[11];
    const float* conv2_w = (const float*)d_in[12];
    const float* conv2_b = (const float*)d_in[13];
    float* out = (float*)d_out;

    float *buf1, *buf2, *gate, *kern1, *kern2;
    cudaGetSymbolAddress((void**)&buf1,  g_buf1);
    cudaGetSymbolAddress((void**)&buf2,  g_buf2);
    cudaGetSymbolAddress((void**)&gate,  g_gate);
    cudaGetSymbolAddress((void**)&kern1, g_kern1);
    cudaGetSymbolAddress((void**)&kern2, g_kern2);

    mlp_kernel<<<dim3(B_, 2), 64>>>(d, da1_k1, da1_k2, da2_k1, da2_k2, kern1, kern2);

    gate_kernel<<<(B_*HW_)/256, 256>>>(x, da1_cw, da1_cb, gate);
    rda_kernel<<<dim3(HW_/256, C_, B_), 256>>>(x, kern1, gate, buf1);

    conv3x3_f32x2<<<dim3(16, C_/COP, B_), 128>>>(buf1, conv1_w, conv1_b, nullptr, buf2, 1);

    gate_kernel<<<(B_*HW_)/256, 256>>>(buf2, da2_cw, da2_cb, gate);
    rda_kernel<<<dim3(HW_/256, C_, B_), 256>>>(buf2, kern2, gate, buf1);

    conv3x3_f32x2<<<dim3(16, C_/COP, B_), 128>>>(buf1, conv2_w, conv2_b, x, out, 0);
}

// round 7
// speedup vs baseline: 3.0588x; 1.2420x over previous
#include <cuda_runtime.h>
#include <math.h>

// ---------------------------------------------------------------------------
// RDAB block: x[16,64,128,128] fp32
// Round 7: FFMA2 conv with OC=8 (LDS amortized over 2x FMA);
//          float4-vectorized rda + gate kernels.
// ---------------------------------------------------------------------------

#define B_   16
#define C_   64
#define H_   128
#define W_   128
#define HW_  (H_*W_)
#define CHW_ (C_*HW_)

typedef unsigned long long u64;
typedef unsigned int u32;

__device__ float g_buf1[(size_t)B_*CHW_];
__device__ float g_buf2[(size_t)B_*CHW_];
__device__ float g_gate[(size_t)B_*HW_];
__device__ float g_kern1[B_*C_*9];
__device__ float g_kern2[B_*C_*9];

__device__ __forceinline__ float leaky01(float v) {
    return v > 0.f ? v : 0.1f * v;
}
__device__ __forceinline__ u64 pk2(float lo, float hi) {
    u64 r; asm("mov.b64 %0, {%1,%2};" : "=l"(r) : "f"(lo), "f"(hi)); return r;
}
__device__ __forceinline__ void fma2(u64& d, u64 a, u64 b) {
    asm("fma.rn.f32x2 %0, %1, %2, %0;" : "+l"(d) : "l"(a), "l"(b));
}
__device__ __forceinline__ float2 unpk(u64 a) {
    float2 v; asm("mov.b64 {%0,%1}, %2;" : "=f"(v.x), "=f"(v.y) : "l"(a)); return v;
}
__device__ __forceinline__ u32 smem_u32(const void* p) {
    u32 a;
    asm("{ .reg .u64 t; cvta.to.shared.u64 t, %1; cvt.u32.u64 %0, t; }"
        : "=r"(a) : "l"(p));
    return a;
}
__device__ __forceinline__ void cp_async16(u32 dst, const void* src) {
    asm volatile("cp.async.ca.shared.global [%0], [%1], 16;\n"
                 :: "r"(dst), "l"(src));
}
__device__ __forceinline__ void cp_commit() {
    asm volatile("cp.async.commit_group;\n");
}
__device__ __forceinline__ void cp_wait_all() {
    asm volatile("cp.async.wait_group 0;\n");
}

// ---------------------------------------------------------------------------
// 1) dynamic-kernel MLP
// ---------------------------------------------------------------------------
__global__ void mlp_kernel(const float* __restrict__ d,
                           const float* __restrict__ k1a, const float* __restrict__ k2a,
                           const float* __restrict__ k1b, const float* __restrict__ k2b,
                           float* __restrict__ kern1, float* __restrict__ kern2)
{
    int b = blockIdx.x;
    int stage = blockIdx.y;
    const float* k1 = stage ? k1b : k1a;
    const float* k2 = stage ? k2b : k2a;
    float* ko = stage ? kern2 : kern1;

    __shared__ float dd[64];
    __shared__ float hid[64];
    int t = threadIdx.x;
    dd[t] = d[b*64 + t];
    __syncthreads();
    float s = 0.f;
#pragma unroll 8
    for (int i = 0; i < 64; i++) s += dd[i] * k1[i*64 + t];
    hid[t] = leaky01(s);
    __syncthreads();
#pragma unroll
    for (int r = 0; r < 9; r++) {
        int o = r*64 + t;
        float s2 = 0.f;
#pragma unroll 8
        for (int i = 0; i < 64; i++) s2 += hid[i] * k2[i*576 + o];
        ko[b*576 + o] = s2;
    }
}

// ---------------------------------------------------------------------------
// 2) gating map, 4 px/thread (float4)
// ---------------------------------------------------------------------------
__global__ void gate_kernel(const float* __restrict__ in,
                            const float* __restrict__ cw,
                            const float* __restrict__ cb,
                            float* __restrict__ M)
{
    __shared__ float scw[C_];
    if (threadIdx.x < C_) scw[threadIdx.x] = cw[threadIdx.x];
    __syncthreads();
    int idx4 = blockIdx.x * blockDim.x + threadIdx.x;   // over B_*HW_/4
    int b   = idx4 / (HW_/4);
    int hw4 = idx4 - b * (HW_/4);
    const float* p = in + (size_t)b * CHW_ + hw4 * 4;
    float bias = cb[0];
    float4 s = make_float4(bias, bias, bias, bias);
#pragma unroll 8
    for (int c = 0; c < C_; c++) {
        float4 v = *(const float4*)(p + (size_t)c * HW_);
        float w = scw[c];
        s.x += w * v.x; s.y += w * v.y; s.z += w * v.z; s.w += w * v.w;
    }
    float4 r;
    r.x = 1.f / (1.f + expf(-s.x));
    r.y = 1.f / (1.f + expf(-s.y));
    r.z = 1.f / (1.f + expf(-s.z));
    r.w = 1.f / (1.f + expf(-s.w));
    *(float4*)&M[(size_t)b * HW_ + hw4 * 4] = r;
}

// ---------------------------------------------------------------------------
// 3) fused RDA, 4 px/thread (float4):
//    out = leaky( leaky(dwconv3x3(in,kern)) * M + in )
// ---------------------------------------------------------------------------
__global__ void rda_kernel(const float* __restrict__ in,
                           const float* __restrict__ kern,
                           const float* __restrict__ M,
                           float* __restrict__ out)
{
    int idx4 = blockIdx.x * blockDim.x + threadIdx.x;  // 0..HW_/4-1
    int c = blockIdx.y;
    int b = blockIdx.z;
    int h  = idx4 >> 5;            // 128 rows
    int wq = (idx4 & 31) * 4;      // 0,4,...,124

    const float* k = kern + (b*C_ + c) * 9;
    float kk[9];
#pragma unroll
    for (int i = 0; i < 9; i++) kk[i] = k[i];

    const float* p = in + ((size_t)b*C_ + c) * HW_;

    float4 dw = make_float4(0.f, 0.f, 0.f, 0.f);
    float4 mid_c = *(const float4*)(p + h * W_ + wq);   // center row, own px

#pragma unroll
    for (int r = 0; r < 3; r++) {
        int gy = h - 1 + r;
        if (gy < 0 || gy >= H_) continue;
        const float* rowp = p + gy * W_;
        float4 mid = (r == 1) ? mid_c : *(const float4*)(rowp + wq);
        float left  = (wq > 0)   ? rowp[wq - 1] : 0.f;
        float right = (wq < 124) ? rowp[wq + 4] : 0.f;
        float t0 = kk[r*3+0], t1 = kk[r*3+1], t2 = kk[r*3+2];
        dw.x += t0*left  + t1*mid.x + t2*mid.y;
        dw.y += t0*mid.x + t1*mid.y + t2*mid.z;
        dw.z += t0*mid.y + t1*mid.z + t2*mid.w;
        dw.w += t0*mid.z + t1*mid.w + t2*right;
    }

    float4 m = *(const float4*)&M[(size_t)b*HW_ + h*W_ + wq];
    float4 o;
    o.x = leaky01(leaky01(dw.x) * m.x + mid_c.x);
    o.y = leaky01(leaky01(dw.y) * m.y + mid_c.y);
    o.z = leaky01(leaky01(dw.z) * m.z + mid_c.z);
    o.w = leaky01(leaky01(dw.w) * m.w + mid_c.w);
    *(float4*)&out[((size_t)b*C_ + c) * HW_ + h*W_ + wq] = o;
}

// ---------------------------------------------------------------------------
// 4) dense 3x3 conv 64->64, FFMA2, OC=8, 2-rows-per-thread.
//    Block 128: lane = tid&31 (pairs at w = 2*lane + 64*m, m=0..1),
//               th = tid>>5 (output rows 2*th, 2*th+1). Tile: 8 rows x 128 w.
//    grid = (16 h-tiles, 8 oc-groups, 16 batches)
// ---------------------------------------------------------------------------
#define COP 8
#define RW  136      // padded row width (floats); 544B = 34*16B

__global__ void __launch_bounds__(128, 3)
conv3x3_f32x2(const float* __restrict__ in,
              const float* __restrict__ wgt,
              const float* __restrict__ bias,
              const float* __restrict__ residual,
              float* __restrict__ out,
              int apply_leaky)
{
    __shared__ __align__(16) float sIn[2][10][RW];   // 10.9 KB
    __shared__ __align__(16) u64 sW2[C_ * COP * 10]; // 40 KB (stride-10 pad)

    int b    = blockIdx.z;
    int co0  = blockIdx.y * COP;
    int h0   = blockIdx.x * 8;
    int tid  = threadIdx.x;
    int lane = tid & 31;
    int th   = tid >> 5;                 // 0..3 -> output rows 2th, 2th+1

    // zero staging buffers once (halo cols + out-of-image rows stay 0)
    for (int i = tid; i < 2 * 10 * RW; i += 128)
        ((float*)sIn)[i] = 0.f;

    // stage packed duplicated weights: sW2[(ci*COP+oc)*10 + tap] = {q,q}
    for (int i = tid; i < C_ * COP * 9; i += 128) {
        int ci  = i / (COP*9);
        int rem = i - ci * (COP*9);
        int oc  = rem / 9;
        int tap = rem - oc * 9;
        float q = wgt[((co0 + oc) * C_ + ci) * 9 + tap];
        sW2[(ci * COP + oc) * 10 + tap] = pk2(q, q);
    }

    const float* inb = in + (size_t)b * CHW_;
    u32 sbase[2] = { smem_u32(&sIn[0][0][0]), smem_u32(&sIn[1][0][0]) };

    __syncthreads();   // zero-fill + weights visible

    // prefetch ci's 10 rows as 16B chunks; idx = r*32+seg, dst j = 4+seg*4
    auto prefetch = [&](int ci, int buf) {
        const float* cp = inb + (size_t)ci * HW_;
#pragma unroll
        for (int k = 0; k < 3; k++) {
            int idx = tid + k * 128;
            if (idx < 320) {
                int r   = idx >> 5;
                int seg = idx & 31;
                int gy  = h0 - 1 + r;
                if (gy >= 0 && gy < H_) {
                    u32 dst = sbase[buf] + (u32)((r * RW + 4 + seg * 4) * 4);
                    cp_async16(dst, cp + gy * W_ + seg * 4);
                }
            }
        }
    };

    u64 acc[COP][2][2];
#pragma unroll
    for (int oc = 0; oc < COP; oc++)
#pragma unroll
        for (int o = 0; o < 2; o++)
#pragma unroll
            for (int m = 0; m < 2; m++) acc[oc][o][m] = 0ull;

    prefetch(0, 0);
    cp_commit();

    for (int ci = 0; ci < C_; ci++) {
        cp_wait_all();
        __syncthreads();                 // buf[ci&1] ready

        if (ci < C_ - 1) {
            prefetch(ci + 1, (ci + 1) & 1);
            cp_commit();
        }

        const float* bufp = &sIn[ci & 1][0][0];

        // load P for 4 staging rows: s = 2*th + k
        u64 Pl[4][2], Pm[4][2], Pr[4][2];
#pragma unroll
        for (int k = 0; k < 4; k++) {
            const float* rowp = bufp + (2 * th + k) * RW;
#pragma unroll
            for (int m = 0; m < 2; m++) {
                int jm = 2 * lane + 64 * m + 4;
                u64 pm = *(const u64*)(rowp + jm);     // (v_w, v_{w+1})
                float2 mid = unpk(pm);
                float vL = rowp[jm - 1];
                float vR = rowp[jm + 2];
                Pm[k][m] = pm;
                Pl[k][m] = pk2(vL, mid.x);
                Pr[k][m] = pk2(mid.y, vR);
            }
        }

#pragma unroll
        for (int oc = 0; oc < COP; oc++) {
            const u64* wp = &sW2[(ci * COP + oc) * 10];
            ulonglong2 q01 = *(const ulonglong2*)(wp);
            ulonglong2 q23 = *(const ulonglong2*)(wp + 2);
            ulonglong2 q45 = *(const ulonglong2*)(wp + 4);
            ulonglong2 q67 = *(const ulonglong2*)(wp + 6);
            u64 W0 = q01.x, W1 = q01.y, W2 = q23.x;
            u64 W3 = q23.y, W4 = q45.x, W5 = q45.y;
            u64 W6 = q67.x, W7 = q67.y, W8 = wp[8];
#pragma unroll
            for (int o = 0; o < 2; o++) {
#pragma unroll
                for (int m = 0; m < 2; m++) {
                    fma2(acc[oc][o][m], Pl[o    ][m], W0);
                    fma2(acc[oc][o][m], Pm[o    ][m], W1);
                    fma2(acc[oc][o][m], Pr[o    ][m], W2);
                    fma2(acc[oc][o][m], Pl[o + 1][m], W3);
                    fma2(acc[oc][o][m], Pm[o + 1][m], W4);
                    fma2(acc[oc][o][m], Pr[o + 1][m], W5);
                    fma2(acc[oc][o][m], Pl[o + 2][m], W6);
                    fma2(acc[oc][o][m], Pm[o + 2][m], W7);
                    fma2(acc[oc][o][m], Pr[o + 2][m], W8);
                }
            }
        }
        __syncthreads();                 // done reading buf[ci&1]
    }

    // epilogue
#pragma unroll
    for (int oc = 0; oc < COP; oc++) {
        float bv = bias[co0 + oc];
#pragma unroll
        for (int o = 0; o < 2; o++) {
            int row = h0 + 2 * th + o;
            size_t rowbase = (((size_t)b * C_ + co0 + oc) * H_ + row) * W_;
#pragma unroll
            for (int m = 0; m < 2; m++) {
                int w = 2 * lane + 64 * m;
                float2 v = unpk(acc[oc][o][m]);
                v.x += bv; v.y += bv;
                if (apply_leaky) { v.x = leaky01(v.x); v.y = leaky01(v.y); }
                if (residual) {
                    const float2 rv = *(const float2*)&residual[rowbase + w];
                    v.x += rv.x; v.y += rv.y;
                }
                *(float2*)&out[rowbase + w] = v;
            }
        }
    }
}

// ---------------------------------------------------------------------------
// launch
// ---------------------------------------------------------------------------
extern "C" void kernel_launch(void* const* d_in, const int* in_sizes, int n_in,
                              void* d_out, int out_size)
{
    const float* x       = (const float*)d_in[0];
    const float* d       = (const float*)d_in[1];
    const float* da1_k1  = (const float*)d_in[2];
    const float* da1_k2  = (const float*)d_in[3];
    const float* da1_cw  = (const float*)d_in[4];
    const float* da1_cb  = (const float*)d_in[5];
    const float* da2_k1  = (const float*)d_in[6];
    const float* da2_k2  = (const float*)d_in[7];
    const float* da2_cw  = (const float*)d_in[8];
    const float* da2_cb  = (const float*)d_in[9];
    const float* conv1_w = (const float*)d_in[10];
    const float* conv1_b = (const float*)d_in[11];
    const float* conv2_w = (const float*)d_in[12];
    const float* conv2_b = (const float*)d_in[13];
    float* out = (float*)d_out;

    float *buf1, *buf2, *gate, *kern1, *kern2;
    cudaGetSymbolAddress((void**)&buf1,  g_buf1);
    cudaGetSymbolAddress((void**)&buf2,  g_buf2);
    cudaGetSymbolAddress((void**)&gate,  g_gate);
    cudaGetSymbolAddress((void**)&kern1, g_kern1);
    cudaGetSymbolAddress((void**)&kern2, g_kern2);

    mlp_kernel<<<dim3(B_, 2), 64>>>(d, da1_k1, da1_k2, da2_k1, da2_k2, kern1, kern2);

    gate_kernel<<<(B_*HW_/4)/256, 256>>>(x, da1_cw, da1_cb, gate);
    rda_kernel<<<dim3(HW_/4/256, C_, B_), 256>>>(x, kern1, gate, buf1);

    conv3x3_f32x2<<<dim3(16, C_/COP, B_), 128>>>(buf1, conv1_w, conv1_b, nullptr, buf2, 1);

    gate_kernel<<<(B_*HW_/4)/256, 256>>>(buf2, da2_cw, da2_cb, gate);
    rda_kernel<<<dim3(HW_/4/256, C_, B_), 256>>>(buf2, kern2, gate, buf1);

    conv3x3_f32x2<<<dim3(16, C_/COP, B_), 128>>>(buf1, conv2_w, conv2_b, x, out, 0);
}

// round 8
// speedup vs baseline: 3.0652x; 1.0021x over previous
#include <cuda_runtime.h>
#include <math.h>

// ---------------------------------------------------------------------------
// RDAB block: x[16,64,128,128] fp32
// Round 7: FFMA2 conv with OC=8 (LDS amortized over 2x FMA);
//          float4-vectorized rda + gate kernels.
// ---------------------------------------------------------------------------

#define B_   16
#define C_   64
#define H_   128
#define W_   128
#define HW_  (H_*W_)
#define CHW_ (C_*HW_)

typedef unsigned long long u64;
typedef unsigned int u32;

__device__ float g_buf1[(size_t)B_*CHW_];
__device__ float g_buf2[(size_t)B_*CHW_];
__device__ float g_gate[(size_t)B_*HW_];
__device__ float g_kern1[B_*C_*9];
__device__ float g_kern2[B_*C_*9];

__device__ __forceinline__ float leaky01(float v) {
    return v > 0.f ? v : 0.1f * v;
}
__device__ __forceinline__ u64 pk2(float lo, float hi) {
    u64 r; asm("mov.b64 %0, {%1,%2};" : "=l"(r) : "f"(lo), "f"(hi)); return r;
}
__device__ __forceinline__ void fma2(u64& d, u64 a, u64 b) {
    asm("fma.rn.f32x2 %0, %1, %2, %0;" : "+l"(d) : "l"(a), "l"(b));
}
__device__ __forceinline__ float2 unpk(u64 a) {
    float2 v; asm("mov.b64 {%0,%1}, %2;" : "=f"(v.x), "=f"(v.y) : "l"(a)); return v;
}
__device__ __forceinline__ u32 smem_u32(const void* p) {
    u32 a;
    asm("{ .reg .u64 t; cvta.to.shared.u64 t, %1; cvt.u32.u64 %0, t; }"
        : "=r"(a) : "l"(p));
    return a;
}
__device__ __forceinline__ void cp_async16(u32 dst, const void* src) {
    asm volatile("cp.async.ca.shared.global [%0], [%1], 16;\n"
                 :: "r"(dst), "l"(src));
}
__device__ __forceinline__ void cp_commit() {
    asm volatile("cp.async.commit_group;\n");
}
__device__ __forceinline__ void cp_wait_all() {
    asm volatile("cp.async.wait_group 0;\n");
}

// ---------------------------------------------------------------------------
// 1) dynamic-kernel MLP
// ---------------------------------------------------------------------------
__global__ void mlp_kernel(const float* __restrict__ d,
                           const float* __restrict__ k1a, const float* __restrict__ k2a,
                           const float* __restrict__ k1b, const float* __restrict__ k2b,
                           float* __restrict__ kern1, float* __restrict__ kern2)
{
    int b = blockIdx.x;
    int stage = blockIdx.y;
    const float* k1 = stage ? k1b : k1a;
    const float* k2 = stage ? k2b : k2a;
    float* ko = stage ? kern2 : kern1;

    __shared__ float dd[64];
    __shared__ float hid[64];
    int t = threadIdx.x;
    dd[t] = d[b*64 + t];
    __syncthreads();
    float s = 0.f;
#pragma unroll 8
    for (int i = 0; i < 64; i++) s += dd[i] * k1[i*64 + t];
    hid[t] = leaky01(s);
    __syncthreads();
#pragma unroll
    for (int r = 0; r < 9; r++) {
        int o = r*64 + t;
        float s2 = 0.f;
#pragma unroll 8
        for (int i = 0; i < 64; i++) s2 += hid[i] * k2[i*576 + o];
        ko[b*576 + o] = s2;
    }
}

// ---------------------------------------------------------------------------
// 2) gating map, 4 px/thread (float4)
// ---------------------------------------------------------------------------
__global__ void gate_kernel(const float* __restrict__ in,
                            const float* __restrict__ cw,
                            const float* __restrict__ cb,
                            float* __restrict__ M)
{
    __shared__ float scw[C_];
    if (threadIdx.x < C_) scw[threadIdx.x] = cw[threadIdx.x];
    __syncthreads();
    int idx4 = blockIdx.x * blockDim.x + threadIdx.x;   // over B_*HW_/4
    int b   = idx4 / (HW_/4);
    int hw4 = idx4 - b * (HW_/4);
    const float* p = in + (size_t)b * CHW_ + hw4 * 4;
    float bias = cb[0];
    float4 s = make_float4(bias, bias, bias, bias);
#pragma unroll 8
    for (int c = 0; c < C_; c++) {
        float4 v = *(const float4*)(p + (size_t)c * HW_);
        float w = scw[c];
        s.x += w * v.x; s.y += w * v.y; s.z += w * v.z; s.w += w * v.w;
    }
    float4 r;
    r.x = 1.f / (1.f + expf(-s.x));
    r.y = 1.f / (1.f + expf(-s.y));
    r.z = 1.f / (1.f + expf(-s.z));
    r.w = 1.f / (1.f + expf(-s.w));
    *(float4*)&M[(size_t)b * HW_ + hw4 * 4] = r;
}

// ---------------------------------------------------------------------------
// 3) fused RDA, 4 px/thread (float4):
//    out = leaky( leaky(dwconv3x3(in,kern)) * M + in )
// ---------------------------------------------------------------------------
__global__ void rda_kernel(const float* __restrict__ in,
                           const float* __restrict__ kern,
                           const float* __restrict__ M,
                           float* __restrict__ out)
{
    int idx4 = blockIdx.x * blockDim.x + threadIdx.x;  // 0..HW_/4-1
    int c = blockIdx.y;
    int b = blockIdx.z;
    int h  = idx4 >> 5;            // 128 rows
    int wq = (idx4 & 31) * 4;      // 0,4,...,124

    const float* k = kern + (b*C_ + c) * 9;
    float kk[9];
#pragma unroll
    for (int i = 0; i < 9; i++) kk[i] = k[i];

    const float* p = in + ((size_t)b*C_ + c) * HW_;

    float4 dw = make_float4(0.f, 0.f, 0.f, 0.f);
    float4 mid_c = *(const float4*)(p + h * W_ + wq);   // center row, own px

#pragma unroll
    for (int r = 0; r < 3; r++) {
        int gy = h - 1 + r;
        if (gy < 0 || gy >= H_) continue;
        const float* rowp = p + gy * W_;
        float4 mid = (r == 1) ? mid_c : *(const float4*)(rowp + wq);
        float left  = (wq > 0)   ? rowp[wq - 1] : 0.f;
        float right = (wq < 124) ? rowp[wq + 4] : 0.f;
        float t0 = kk[r*3+0], t1 = kk[r*3+1], t2 = kk[r*3+2];
        dw.x += t0*left  + t1*mid.x + t2*mid.y;
        dw.y += t0*mid.x + t1*mid.y + t2*mid.z;
        dw.z += t0*mid.y + t1*mid.z + t2*mid.w;
        dw.w += t0*mid.z + t1*mid.w + t2*right;
    }

    float4 m = *(const float4*)&M[(size_t)b*HW_ + h*W_ + wq];
    float4 o;
    o.x = leaky01(leaky01(dw.x) * m.x + mid_c.x);
    o.y = leaky01(leaky01(dw.y) * m.y + mid_c.y);
    o.z = leaky01(leaky01(dw.z) * m.z + mid_c.z);
    o.w = leaky01(leaky01(dw.w) * m.w + mid_c.w);
    *(float4*)&out[((size_t)b*C_ + c) * HW_ + h*W_ + wq] = o;
}

// ---------------------------------------------------------------------------
// 4) dense 3x3 conv 64->64, FFMA2, OC=8, 2-rows-per-thread.
//    Block 128: lane = tid&31 (pairs at w = 2*lane + 64*m, m=0..1),
//               th = tid>>5 (output rows 2*th, 2*th+1). Tile: 8 rows x 128 w.
//    grid = (16 h-tiles, 8 oc-groups, 16 batches)
// ---------------------------------------------------------------------------
#define COP 8
#define RW  136      // padded row width (floats); 544B = 34*16B

__global__ void __launch_bounds__(128, 3)
conv3x3_f32x2(const float* __restrict__ in,
              const float* __restrict__ wgt,
              const float* __restrict__ bias,
              const float* __restrict__ residual,
              float* __restrict__ out,
              int apply_leaky)
{
    __shared__ __align__(16) float sIn[2][10][RW];   // 10.9 KB
    __shared__ __align__(16) u64 sW2[C_ * COP * 10]; // 40 KB (stride-10 pad)

    int b    = blockIdx.z;
    int co0  = blockIdx.y * COP;
    int h0   = blockIdx.x * 8;
    int tid  = threadIdx.x;
    int lane = tid & 31;
    int th   = tid >> 5;                 // 0..3 -> output rows 2th, 2th+1

    // zero staging buffers once (halo cols + out-of-image rows stay 0)
    for (int i = tid; i < 2 * 10 * RW; i += 128)
        ((float*)sIn)[i] = 0.f;

    // stage packed duplicated weights: sW2[(ci*COP+oc)*10 + tap] = {q,q}
    for (int i = tid; i < C_ * COP * 9; i += 128) {
        int ci  = i / (COP*9);
        int rem = i - ci * (COP*9);
        int oc  = rem / 9;
        int tap = rem - oc * 9;
        float q = wgt[((co0 + oc) * C_ + ci) * 9 + tap];
        sW2[(ci * COP + oc) * 10 + tap] = pk2(q, q);
    }

    const float* inb = in + (size_t)b * CHW_;
    u32 sbase[2] = { smem_u32(&sIn[0][0][0]), smem_u32(&sIn[1][0][0]) };

    __syncthreads();   // zero-fill + weights visible

    // prefetch ci's 10 rows as 16B chunks; idx = r*32+seg, dst j = 4+seg*4
    auto prefetch = [&](int ci, int buf) {
        const float* cp = inb + (size_t)ci * HW_;
#pragma unroll
        for (int k = 0; k < 3; k++) {
            int idx = tid + k * 128;
            if (idx < 320) {
                int r   = idx >> 5;
                int seg = idx & 31;
                int gy  = h0 - 1 + r;
                if (gy >= 0 && gy < H_) {
                    u32 dst = sbase[buf] + (u32)((r * RW + 4 + seg * 4) * 4);
                    cp_async16(dst, cp + gy * W_ + seg * 4);
                }
            }
        }
    };

    u64 acc[COP][2][2];
#pragma unroll
    for (int oc = 0; oc < COP; oc++)
#pragma unroll
        for (int o = 0; o < 2; o++)
#pragma unroll
            for (int m = 0; m < 2; m++) acc[oc][o][m] = 0ull;

    prefetch(0, 0);
    cp_commit();

    for (int ci = 0; ci < C_; ci++) {
        cp_wait_all();
        __syncthreads();                 // buf[ci&1] ready

        if (ci < C_ - 1) {
            prefetch(ci + 1, (ci + 1) & 1);
            cp_commit();
        }

        const float* bufp = &sIn[ci & 1][0][0];

        // load P for 4 staging rows: s = 2*th + k
        u64 Pl[4][2], Pm[4][2], Pr[4][2];
#pragma unroll
        for (int k = 0; k < 4; k++) {
            const float* rowp = bufp + (2 * th + k) * RW;
#pragma unroll
            for (int m = 0; m < 2; m++) {
                int jm = 2 * lane + 64 * m + 4;
                u64 pm = *(const u64*)(rowp + jm);     // (v_w, v_{w+1})
                float2 mid = unpk(pm);
                float vL = rowp[jm - 1];
                float vR = rowp[jm + 2];
                Pm[k][m] = pm;
                Pl[k][m] = pk2(vL, mid.x);
                Pr[k][m] = pk2(mid.y, vR);
            }
        }

#pragma unroll
        for (int oc = 0; oc < COP; oc++) {
            const u64* wp = &sW2[(ci * COP + oc) * 10];
            ulonglong2 q01 = *(const ulonglong2*)(wp);
            ulonglong2 q23 = *(const ulonglong2*)(wp + 2);
            ulonglong2 q45 = *(const ulonglong2*)(wp + 4);
            ulonglong2 q67 = *(const ulonglong2*)(wp + 6);
            u64 W0 = q01.x, W1 = q01.y, W2 = q23.x;
            u64 W3 = q23.y, W4 = q45.x, W5 = q45.y;
            u64 W6 = q67.x, W7 = q67.y, W8 = wp[8];
#pragma unroll
            for (int o = 0; o < 2; o++) {
#pragma unroll
                for (int m = 0; m < 2; m++) {
                    fma2(acc[oc][o][m], Pl[o    ][m], W0);
                    fma2(acc[oc][o][m], Pm[o    ][m], W1);
                    fma2(acc[oc][o][m], Pr[o    ][m], W2);
                    fma2(acc[oc][o][m], Pl[o + 1][m], W3);
                    fma2(acc[oc][o][m], Pm[o + 1][m], W4);
                    fma2(acc[oc][o][m], Pr[o + 1][m], W5);
                    fma2(acc[oc][o][m], Pl[o + 2][m], W6);
                    fma2(acc[oc][o][m], Pm[o + 2][m], W7);
                    fma2(acc[oc][o][m], Pr[o + 2][m], W8);
                }
            }
        }
        __syncthreads();                 // done reading buf[ci&1]
    }

    // epilogue
#pragma unroll
    for (int oc = 0; oc < COP; oc++) {
        float bv = bias[co0 + oc];
#pragma unroll
        for (int o = 0; o < 2; o++) {
            int row = h0 + 2 * th + o;
            size_t rowbase = (((size_t)b * C_ + co0 + oc) * H_ + row) * W_;
#pragma unroll
            for (int m = 0; m < 2; m++) {
                int w = 2 * lane + 64 * m;
                float2 v = unpk(acc[oc][o][m]);
                v.x += bv; v.y += bv;
                if (apply_leaky) { v.x = leaky01(v.x); v.y = leaky01(v.y); }
                if (residual) {
                    const float2 rv = *(const float2*)&residual[rowbase + w];
                    v.x += rv.x; v.y += rv.y;
                }
                *(float2*)&out[rowbase + w] = v;
            }
        }
    }
}

// ---------------------------------------------------------------------------
// launch
// ---------------------------------------------------------------------------
extern "C" void kernel_launch(void* const* d_in, const int* in_sizes, int n_in,
                              void* d_out, int out_size)
{
    const float* x       = (const float*)d_in[0];
    const float* d       = (const float*)d_in[1];
    const float* da1_k1  = (const float*)d_in[2];
    const float* da1_k2  = (const float*)d_in[3];
    const float* da1_cw  = (const float*)d_in[4];
    const float* da1_cb  = (const float*)d_in[5];
    const float* da2_k1  = (const float*)d_in[6];
    const float* da2_k2  = (const float*)d_in[7];
    const float* da2_cw  = (const float*)d_in[8];
    const float* da2_cb  = (const float*)d_in[9];
    const float* conv1_w = (const float*)d_in[10];
    const float* conv1_b = (const float*)d_in[11];
    const float* conv2_w = (const float*)d_in[12];
    const float* conv2_b = (const float*)d_in[13];
    float* out = (float*)d_out;

    float *buf1, *buf2, *gate, *kern1, *kern2;
    cudaGetSymbolAddress((void**)&buf1,  g_buf1);
    cudaGetSymbolAddress((void**)&buf2,  g_buf2);
    cudaGetSymbolAddress((void**)&gate,  g_gate);
    cudaGetSymbolAddress((void**)&kern1, g_kern1);
    cudaGetSymbolAddress((void**)&kern2, g_kern2);

    mlp_kernel<<<dim3(B_, 2), 64>>>(d, da1_k1, da1_k2, da2_k1, da2_k2, kern1, kern2);

    gate_kernel<<<(B_*HW_/4)/256, 256>>>(x, da1_cw, da1_cb, gate);
    rda_kernel<<<dim3(HW_/4/256, C_, B_), 256>>>(x, kern1, gate, buf1);

    conv3x3_f32x2<<<dim3(16, C_/COP, B_), 128>>>(buf1, conv1_w, conv1_b, nullptr, buf2, 1);

    gate_kernel<<<(B_*HW_/4)/256, 256>>>(buf2, da2_cw, da2_cb, gate);
    rda_kernel<<<dim3(HW_/4/256, C_, B_), 256>>>(buf2, kern2, gate, buf1);

    conv3x3_f32x2<<<dim3(16, C_/COP, B_), 128>>>(buf1, conv2_w, conv2_b, x, out, 0);
}

// round 10
// speedup vs baseline: 4.5499x; 1.4844x over previous
#include <cuda_runtime.h>
#include <cuda_bf16.h>
#include <math.h>

// ---------------------------------------------------------------------------
// RDAB block: x[16,64,128,128] fp32
// Round 10: dense 3x3 convs via mma.sync.m16n8k16 bf16 (baseline PTX, maps to
// HMMA on sm_103 — tcgen05 unavailable: harness targets compute_103, not 'a').
// D[64co,128px] = W[64,576] x Im2col[576,128], bf16 hi/lo split, fp32 accum.
// ---------------------------------------------------------------------------

#define B_   16
#define C_   64
#define H_   128
#define W_   128
#define HW_  (H_*W_)
#define CHW_ (C_*HW_)

typedef unsigned long long u64;
typedef unsigned int u32;
typedef unsigned short u16;

__device__ u32   g_buf1[(size_t)B_*CHW_];   // packed (bf16hi<<16)|bf16lo
__device__ float g_buf2[(size_t)B_*CHW_];
__device__ float g_gate[(size_t)B_*HW_];
__device__ float g_kern1[B_*C_*9];
__device__ float g_kern2[B_*C_*9];
// fragment-ordered weights: [conv2][chunk4][step9][mt4][half2][lane32][reg4] u32
__device__ u32   g_wA[2*4*9*4*2*32*4];

__device__ __forceinline__ float leaky01(float v) { return v > 0.f ? v : 0.1f*v; }

__device__ __forceinline__ u32 pack_hilo(float v) {
    __nv_bfloat16 h = __float2bfloat16(v);
    float vh = __bfloat162float(h);
    __nv_bfloat16 l = __float2bfloat16(v - vh);
    u16 hb = *reinterpret_cast<u16*>(&h);
    u16 lb = *reinterpret_cast<u16*>(&l);
    return ((u32)hb << 16) | (u32)lb;
}

__device__ __forceinline__ void mma16816(float* c, const u32* a, u32 b0, u32 b1) {
    asm volatile(
        "mma.sync.aligned.m16n8k16.row.col.f32.bf16.bf16.f32 "
        "{%0,%1,%2,%3}, {%4,%5,%6,%7}, {%8,%9}, {%0,%1,%2,%3};"
        : "+f"(c[0]), "+f"(c[1]), "+f"(c[2]), "+f"(c[3])
        : "r"(a[0]), "r"(a[1]), "r"(a[2]), "r"(a[3]), "r"(b0), "r"(b1));
}

// ---------------------------------------------------------------------------
// 1) dynamic-kernel MLP
// ---------------------------------------------------------------------------
__global__ void mlp_kernel(const float* __restrict__ d,
                           const float* __restrict__ k1a, const float* __restrict__ k2a,
                           const float* __restrict__ k1b, const float* __restrict__ k2b,
                           float* __restrict__ kern1, float* __restrict__ kern2)
{
    int b = blockIdx.x, stage = blockIdx.y;
    const float* k1 = stage ? k1b : k1a;
    const float* k2 = stage ? k2b : k2a;
    float* ko = stage ? kern2 : kern1;
    __shared__ float dd[64], hid[64];
    int t = threadIdx.x;
    dd[t] = d[b*64 + t];
    __syncthreads();
    float s = 0.f;
#pragma unroll 8
    for (int i = 0; i < 64; i++) s += dd[i] * k1[i*64 + t];
    hid[t] = leaky01(s);
    __syncthreads();
#pragma unroll
    for (int r = 0; r < 9; r++) {
        int o = r*64 + t;
        float s2 = 0.f;
#pragma unroll 8
        for (int i = 0; i < 64; i++) s2 += hid[i] * k2[i*576 + o];
        ko[b*576 + o] = s2;
    }
}

// ---------------------------------------------------------------------------
// 2) gating map, float4
// ---------------------------------------------------------------------------
__global__ void gate_kernel(const float* __restrict__ in,
                            const float* __restrict__ cw,
                            const float* __restrict__ cb,
                            float* __restrict__ M)
{
    __shared__ float scw[C_];
    if (threadIdx.x < C_) scw[threadIdx.x] = cw[threadIdx.x];
    __syncthreads();
    int idx4 = blockIdx.x * blockDim.x + threadIdx.x;
    int b = idx4 / (HW_/4);
    int hw4 = idx4 - b * (HW_/4);
    const float* p = in + (size_t)b * CHW_ + hw4 * 4;
    float bias = cb[0];
    float4 s = make_float4(bias, bias, bias, bias);
#pragma unroll 8
    for (int c = 0; c < C_; c++) {
        float4 v = *(const float4*)(p + (size_t)c * HW_);
        float w = scw[c];
        s.x += w*v.x; s.y += w*v.y; s.z += w*v.z; s.w += w*v.w;
    }
    float4 r;
    r.x = 1.f/(1.f+expf(-s.x)); r.y = 1.f/(1.f+expf(-s.y));
    r.z = 1.f/(1.f+expf(-s.z)); r.w = 1.f/(1.f+expf(-s.w));
    *(float4*)&M[(size_t)b*HW_ + hw4*4] = r;
}

// ---------------------------------------------------------------------------
// 3) fused RDA, float4 — writes PACKED (bf16hi<<16|bf16lo)
// ---------------------------------------------------------------------------
__global__ void rda_kernel(const float* __restrict__ in,
                           const float* __restrict__ kern,
                           const float* __restrict__ M,
                           u32* __restrict__ outp)
{
    int idx4 = blockIdx.x * blockDim.x + threadIdx.x;
    int c = blockIdx.y, b = blockIdx.z;
    int h  = idx4 >> 5;
    int wq = (idx4 & 31) * 4;

    const float* k = kern + (b*C_ + c) * 9;
    float kk[9];
#pragma unroll
    for (int i = 0; i < 9; i++) kk[i] = k[i];

    const float* p = in + ((size_t)b*C_ + c) * HW_;
    float4 dw = make_float4(0.f, 0.f, 0.f, 0.f);
    float4 mid_c = *(const float4*)(p + h * W_ + wq);

#pragma unroll
    for (int r = 0; r < 3; r++) {
        int gy = h - 1 + r;
        if (gy < 0 || gy >= H_) continue;
        const float* rowp = p + gy * W_;
        float4 mid = (r == 1) ? mid_c : *(const float4*)(rowp + wq);
        float left  = (wq > 0)   ? rowp[wq - 1] : 0.f;
        float right = (wq < 124) ? rowp[wq + 4] : 0.f;
        float t0 = kk[r*3+0], t1 = kk[r*3+1], t2 = kk[r*3+2];
        dw.x += t0*left  + t1*mid.x + t2*mid.y;
        dw.y += t0*mid.x + t1*mid.y + t2*mid.z;
        dw.z += t0*mid.y + t1*mid.z + t2*mid.w;
        dw.w += t0*mid.z + t1*mid.w + t2*right;
    }

    float4 m = *(const float4*)&M[(size_t)b*HW_ + h*W_ + wq];
    uint4 o;
    o.x = pack_hilo(leaky01(leaky01(dw.x)*m.x + mid_c.x));
    o.y = pack_hilo(leaky01(leaky01(dw.y)*m.y + mid_c.y));
    o.z = pack_hilo(leaky01(leaky01(dw.z)*m.z + mid_c.z));
    o.w = pack_hilo(leaky01(leaky01(dw.w)*m.w + mid_c.w));
    *(uint4*)&outp[((size_t)b*C_ + c)*HW_ + h*W_ + wq] = o;
}

// ---------------------------------------------------------------------------
// 3b) weight prep: fp32 OIHW -> bf16 hi/lo in m16n8k16 A-fragment order.
//     idx -> (conv, chunk, step, mtile, half, lane, reg); one u32 per thread.
//     A-frag (sm_80 layout): reg r: row = g + (r&1)*8, k = 2*tig + (r>>1)*8.
// ---------------------------------------------------------------------------
__global__ void wprep_kernel(const float* __restrict__ w1,
                             const float* __restrict__ w2)
{
    int idx = blockIdx.x * blockDim.x + threadIdx.x;
    if (idx >= 2*4*9*4*2*32*4) return;
    int t = idx;
    int r    = t & 3;  t >>= 2;
    int lane = t & 31; t >>= 5;
    int q    = t & 1;  t >>= 1;
    int mt   = t & 3;  t >>= 2;
    int s9   = t % 9;  t /= 9;
    int chunk= t & 3;  t >>= 2;
    int s2   = t;                      // conv index

    int g = lane >> 2, tig = lane & 3;
    int co = mt*16 + g + (r & 1)*8;
    int k0 = s9*16 + 2*tig + (r >> 1)*8;   // chunk-local k, 0..142
    int k1 = k0 + 1;

    const float* w = s2 ? w2 : w1;
    int ci0 = k0/9, tap0 = k0 - ci0*9;
    int ci1 = k1/9, tap1 = k1 - ci1*9;
    float w0 = w[(co*C_ + chunk*16 + ci0)*9 + tap0];
    float w1v= w[(co*C_ + chunk*16 + ci1)*9 + tap1];

    u16 p0, p1;
    if (q == 0) {
        __nv_bfloat16 h0 = __float2bfloat16(w0), h1 = __float2bfloat16(w1v);
        p0 = *reinterpret_cast<u16*>(&h0); p1 = *reinterpret_cast<u16*>(&h1);
    } else {
        __nv_bfloat16 h0 = __float2bfloat16(w0);
        __nv_bfloat16 l0 = __float2bfloat16(w0 - __bfloat162float(h0));
        __nv_bfloat16 h1 = __float2bfloat16(w1v);
        __nv_bfloat16 l1 = __float2bfloat16(w1v - __bfloat162float(h1));
        p0 = *reinterpret_cast<u16*>(&l0); p1 = *reinterpret_cast<u16*>(&l1);
    }
    g_wA[idx] = ((u32)p1 << 16) | (u32)p0;
}

// ---------------------------------------------------------------------------
// 4) mma.sync conv: one block = one (b,h) row; 128 threads = 4 warps.
//    Warp w: px [w*32, w*32+32), all 64 co. 4 chunks of 16 ci (9 K16-steps).
//    smem: weight fragments 36864 B + packed input 16ci x 3rows x 132 u32.
// ---------------------------------------------------------------------------
#define W_CHUNK_U32 9216                // 36864 B / 4
#define IN_OFF_U32  9216
#define SMEM_DYN    (36864 + 16*3*132*4)

__global__ void __launch_bounds__(128, 3)
conv_mma(const u32* __restrict__ pin,
         const u32* __restrict__ wA,      // fragment weights for this conv
         const float* __restrict__ bias,
         const float* __restrict__ residual,
         float* __restrict__ out,
         int apply_leaky)
{
    extern __shared__ u32 dsm[];
    u32* smW = dsm;                     // [step][mt][half][lane][reg]
    u32* inS = dsm + IN_OFF_U32;        // [(ci*3+row)*132 + j], j = px + tap

    int tid = threadIdx.x;
    int wid = tid >> 5;
    int lane = tid & 31;
    int g = lane >> 2, tig = lane & 3;
    int h = blockIdx.x, b = blockIdx.z;
    int warpbase = wid * 32;

    float D[4][4][4];                   // [mt][nt][c0..c3]
#pragma unroll
    for (int mt = 0; mt < 4; mt++)
#pragma unroll
        for (int nt = 0; nt < 4; nt++)
#pragma unroll
            for (int i = 0; i < 4; i++) D[mt][nt][i] = 0.f;

    for (int chunk = 0; chunk < 4; chunk++) {
        // ---- stage weight fragments (2304 uint4) ----
        {
            const uint4* src = (const uint4*)(wA + chunk * W_CHUNK_U32);
            uint4* dst = (uint4*)smW;
#pragma unroll
            for (int i = 0; i < 18; i++)
                dst[tid + i*128] = src[tid + i*128];
        }
        // ---- stage input: 16 ci x 3 rows x 132 (j = px + tap%3, halo 0) ----
        for (int idx = tid; idx < 16*3*132; idx += 128) {
            int ci = idx / 396;
            int r2 = idx - ci*396;
            int ky = r2 / 132;
            int j  = r2 - ky*132;
            int gy = h - 1 + ky;
            u32 v = 0;
            if (j >= 1 && j <= 128 && gy >= 0 && gy < H_)
                v = pin[(((size_t)b*C_ + chunk*16 + ci)*H_ + gy)*W_ + (j-1)];
            inS[(ci*3 + ky)*132 + j] = v;
        }
        __syncthreads();

#pragma unroll
        for (int s = 0; s < 9; s++) {
            // A fragments: 4 m-tiles x (hi, lo), one LDS.128 each
            uint4 Ah[4], Al[4];
#pragma unroll
            for (int mt = 0; mt < 4; mt++) {
                const u32* base = smW + ((s*4 + mt)*2)*128 + lane*4;
                Ah[mt] = *(const uint4*)(base);
                Al[mt] = *(const uint4*)(base + 128);
            }
#pragma unroll
            for (int nt = 0; nt < 4; nt++) {
                int n = warpbase + nt*8 + g;     // pixel for B fragment
                u32 bh[2], bl[2];
#pragma unroll
                for (int r = 0; r < 2; r++) {
                    int k0 = s*16 + 2*tig + r*8;       // compile-time per unroll
                    int k1 = k0 + 1;
                    int ci0 = k0/9, tap0 = k0 - ci0*9;
                    int ci1 = k1/9, tap1 = k1 - ci1*9;
                    u32 v0 = inS[(ci0*3 + tap0/3)*132 + n + (tap0 % 3)];
                    u32 v1 = inS[(ci1*3 + tap1/3)*132 + n + (tap1 % 3)];
                    bh[r] = __byte_perm(v0, v1, 0x7632);
                    bl[r] = __byte_perm(v0, v1, 0x5410);
                }
#pragma unroll
                for (int mt = 0; mt < 4; mt++) {
                    mma16816(D[mt][nt], (const u32*)&Ah[mt], bh[0], bh[1]);
                    mma16816(D[mt][nt], (const u32*)&Ah[mt], bl[0], bl[1]);
                    mma16816(D[mt][nt], (const u32*)&Al[mt], bh[0], bh[1]);
                }
            }
        }
        __syncthreads();   // done with smem before restaging
    }

    // ---- epilogue: D[mt][nt]: rows co = mt*16+g(+8), cols px = nt*8+2tig(+1)
#pragma unroll
    for (int mt = 0; mt < 4; mt++) {
        int co0 = mt*16 + g;
        float bv0 = bias[co0], bv1 = bias[co0 + 8];
#pragma unroll
        for (int nt = 0; nt < 4; nt++) {
            int px = warpbase + nt*8 + 2*tig;
            size_t o0 = (((size_t)b*C_ + co0    )*H_ + h)*W_ + px;
            size_t o1 = (((size_t)b*C_ + co0 + 8)*H_ + h)*W_ + px;
            float2 v0 = make_float2(D[mt][nt][0] + bv0, D[mt][nt][1] + bv0);
            float2 v1 = make_float2(D[mt][nt][2] + bv1, D[mt][nt][3] + bv1);
            if (apply_leaky) {
                v0.x = leaky01(v0.x); v0.y = leaky01(v0.y);
                v1.x = leaky01(v1.x); v1.y = leaky01(v1.y);
            }
            if (residual) {
                const float2 r0 = *(const float2*)&residual[o0];
                const float2 r1 = *(const float2*)&residual[o1];
                v0.x += r0.x; v0.y += r0.y; v1.x += r1.x; v1.y += r1.y;
            }
            *(float2*)&out[o0] = v0;
            *(float2*)&out[o1] = v1;
        }
    }
}

// ---------------------------------------------------------------------------
// launch
// ---------------------------------------------------------------------------
extern "C" void kernel_launch(void* const* d_in, const int* in_sizes, int n_in,
                              void* d_out, int out_size)
{
    const float* x       = (const float*)d_in[0];
    const float* d       = (const float*)d_in[1];
    const float* da1_k1  = (const float*)d_in[2];
    const float* da1_k2  = (const float*)d_in[3];
    const float* da1_cw  = (const float*)d_in[4];
    const float* da1_cb  = (const float*)d_in[5];
    const float* da2_k1  = (const float*)d_in[6];
    const float* da2_k2  = (const float*)d_in[7];
    const float* da2_cw  = (const float*)d_in[8];
    const float* da2_cb  = (const float*)d_in[9];
    const float* conv1_w = (const float*)d_in[10];
    const float* conv1_b = (const float*)d_in[11];
    const float* conv2_w = (const float*)d_in[12];
    const float* conv2_b = (const float*)d_in[13];
    float* out = (float*)d_out;

    u32 *buf1, *wa; float *buf2, *gate, *kern1, *kern2;
    cudaGetSymbolAddress((void**)&buf1,  g_buf1);
    cudaGetSymbolAddress((void**)&buf2,  g_buf2);
    cudaGetSymbolAddress((void**)&gate,  g_gate);
    cudaGetSymbolAddress((void**)&kern1, g_kern1);
    cudaGetSymbolAddress((void**)&kern2, g_kern2);
    cudaGetSymbolAddress((void**)&wa,    g_wA);

    cudaFuncSetAttribute(conv_mma, cudaFuncAttributeMaxDynamicSharedMemorySize, SMEM_DYN);

    mlp_kernel<<<dim3(B_, 2), 64>>>(d, da1_k1, da1_k2, da2_k1, da2_k2, kern1, kern2);
    wprep_kernel<<<(2*4*9*4*2*32*4 + 255)/256, 256>>>(conv1_w, conv2_w);

    gate_kernel<<<(B_*HW_/4)/256, 256>>>(x, da1_cw, da1_cb, gate);
    rda_kernel<<<dim3(HW_/4/256, C_, B_), 256>>>(x, kern1, gate, buf1);

    conv_mma<<<dim3(H_, 1, B_), 128, SMEM_DYN>>>(buf1, wa, conv1_b, nullptr, buf2, 1);

    gate_kernel<<<(B_*HW_/4)/256, 256>>>(buf2, da2_cw, da2_cb, gate);
    rda_kernel<<<dim3(HW_/4/256, C_, B_), 256>>>(buf2, kern2, gate, buf1);

    conv_mma<<<dim3(H_, 1, B_), 128, SMEM_DYN>>>(buf1, wa + 4*W_CHUNK_U32,
                                                 conv2_b, x, out, 0);
}

// round 11
// speedup vs baseline: 5.4930x; 1.2073x over previous
#include <cuda_runtime.h>
#include <cuda_bf16.h>
#include <math.h>

// ---------------------------------------------------------------------------
// RDAB block: x[16,64,128,128] fp32
// Round 11: mma.sync bf16 conv, pipelined:
//   - 2 rows/block (256 thr, warp-group per row), weights staged once/chunk
//   - cp.async double-buffered weights + inputs (no naked LDG latency)
// ---------------------------------------------------------------------------

#define B_   16
#define C_   64
#define H_   128
#define W_   128
#define HW_  (H_*W_)
#define CHW_ (C_*HW_)

typedef unsigned long long u64;
typedef unsigned int u32;
typedef unsigned short u16;

__device__ u32   g_buf1[(size_t)B_*CHW_];   // packed (bf16hi<<16)|bf16lo
__device__ float g_buf2[(size_t)B_*CHW_];
__device__ float g_gate[(size_t)B_*HW_];
__device__ float g_kern1[B_*C_*9];
__device__ float g_kern2[B_*C_*9];
// fragment-ordered weights: [conv2][chunk4][step9][mt4][half2][lane32][reg4] u32
__device__ u32   g_wA[2*4*9*4*2*32*4];

__device__ __forceinline__ float leaky01(float v) { return v > 0.f ? v : 0.1f*v; }

__device__ __forceinline__ u32 pack_hilo(float v) {
    __nv_bfloat16 h = __float2bfloat16(v);
    float vh = __bfloat162float(h);
    __nv_bfloat16 l = __float2bfloat16(v - vh);
    u16 hb = *reinterpret_cast<u16*>(&h);
    u16 lb = *reinterpret_cast<u16*>(&l);
    return ((u32)hb << 16) | (u32)lb;
}
__device__ __forceinline__ void mma16816(float* c, const u32* a, u32 b0, u32 b1) {
    asm volatile(
        "mma.sync.aligned.m16n8k16.row.col.f32.bf16.bf16.f32 "
        "{%0,%1,%2,%3}, {%4,%5,%6,%7}, {%8,%9}, {%0,%1,%2,%3};"
        : "+f"(c[0]), "+f"(c[1]), "+f"(c[2]), "+f"(c[3])
        : "r"(a[0]), "r"(a[1]), "r"(a[2]), "r"(a[3]), "r"(b0), "r"(b1));
}
__device__ __forceinline__ u32 smem_u32(const void* p) {
    u32 a;
    asm("{ .reg .u64 t; cvta.to.shared.u64 t, %1; cvt.u32.u64 %0, t; }"
        : "=r"(a) : "l"(p));
    return a;
}
__device__ __forceinline__ void cp_async16(u32 dst, const void* src) {
    asm volatile("cp.async.ca.shared.global [%0], [%1], 16;\n" :: "r"(dst), "l"(src));
}
__device__ __forceinline__ void cp_commit() { asm volatile("cp.async.commit_group;\n"); }
__device__ __forceinline__ void cp_wait_all() { asm volatile("cp.async.wait_group 0;\n"); }

// ---------------------------------------------------------------------------
// 1) dynamic-kernel MLP
// ---------------------------------------------------------------------------
__global__ void mlp_kernel(const float* __restrict__ d,
                           const float* __restrict__ k1a, const float* __restrict__ k2a,
                           const float* __restrict__ k1b, const float* __restrict__ k2b,
                           float* __restrict__ kern1, float* __restrict__ kern2)
{
    int b = blockIdx.x, stage = blockIdx.y;
    const float* k1 = stage ? k1b : k1a;
    const float* k2 = stage ? k2b : k2a;
    float* ko = stage ? kern2 : kern1;
    __shared__ float dd[64], hid[64];
    int t = threadIdx.x;
    dd[t] = d[b*64 + t];
    __syncthreads();
    float s = 0.f;
#pragma unroll 8
    for (int i = 0; i < 64; i++) s += dd[i] * k1[i*64 + t];
    hid[t] = leaky01(s);
    __syncthreads();
#pragma unroll
    for (int r = 0; r < 9; r++) {
        int o = r*64 + t;
        float s2 = 0.f;
#pragma unroll 8
        for (int i = 0; i < 64; i++) s2 += hid[i] * k2[i*576 + o];
        ko[b*576 + o] = s2;
    }
}

// ---------------------------------------------------------------------------
// 2) gating map, float4
// ---------------------------------------------------------------------------
__global__ void gate_kernel(const float* __restrict__ in,
                            const float* __restrict__ cw,
                            const float* __restrict__ cb,
                            float* __restrict__ M)
{
    __shared__ float scw[C_];
    if (threadIdx.x < C_) scw[threadIdx.x] = cw[threadIdx.x];
    __syncthreads();
    int idx4 = blockIdx.x * blockDim.x + threadIdx.x;
    int b = idx4 / (HW_/4);
    int hw4 = idx4 - b * (HW_/4);
    const float* p = in + (size_t)b * CHW_ + hw4 * 4;
    float bias = cb[0];
    float4 s = make_float4(bias, bias, bias, bias);
#pragma unroll 8
    for (int c = 0; c < C_; c++) {
        float4 v = *(const float4*)(p + (size_t)c * HW_);
        float w = scw[c];
        s.x += w*v.x; s.y += w*v.y; s.z += w*v.z; s.w += w*v.w;
    }
    float4 r;
    r.x = 1.f/(1.f+expf(-s.x)); r.y = 1.f/(1.f+expf(-s.y));
    r.z = 1.f/(1.f+expf(-s.z)); r.w = 1.f/(1.f+expf(-s.w));
    *(float4*)&M[(size_t)b*HW_ + hw4*4] = r;
}

// ---------------------------------------------------------------------------
// 3) fused RDA, float4 — writes PACKED (bf16hi<<16|bf16lo)
// ---------------------------------------------------------------------------
__global__ void rda_kernel(const float* __restrict__ in,
                           const float* __restrict__ kern,
                           const float* __restrict__ M,
                           u32* __restrict__ outp)
{
    int idx4 = blockIdx.x * blockDim.x + threadIdx.x;
    int c = blockIdx.y, b = blockIdx.z;
    int h  = idx4 >> 5;
    int wq = (idx4 & 31) * 4;

    const float* k = kern + (b*C_ + c) * 9;
    float kk[9];
#pragma unroll
    for (int i = 0; i < 9; i++) kk[i] = k[i];

    const float* p = in + ((size_t)b*C_ + c) * HW_;
    float4 dw = make_float4(0.f, 0.f, 0.f, 0.f);
    float4 mid_c = *(const float4*)(p + h * W_ + wq);

#pragma unroll
    for (int r = 0; r < 3; r++) {
        int gy = h - 1 + r;
        if (gy < 0 || gy >= H_) continue;
        const float* rowp = p + gy * W_;
        float4 mid = (r == 1) ? mid_c : *(const float4*)(rowp + wq);
        float left  = (wq > 0)   ? rowp[wq - 1] : 0.f;
        float right = (wq < 124) ? rowp[wq + 4] : 0.f;
        float t0 = kk[r*3+0], t1 = kk[r*3+1], t2 = kk[r*3+2];
        dw.x += t0*left  + t1*mid.x + t2*mid.y;
        dw.y += t0*mid.x + t1*mid.y + t2*mid.z;
        dw.z += t0*mid.y + t1*mid.z + t2*mid.w;
        dw.w += t0*mid.z + t1*mid.w + t2*right;
    }

    float4 m = *(const float4*)&M[(size_t)b*HW_ + h*W_ + wq];
    uint4 o;
    o.x = pack_hilo(leaky01(leaky01(dw.x)*m.x + mid_c.x));
    o.y = pack_hilo(leaky01(leaky01(dw.y)*m.y + mid_c.y));
    o.z = pack_hilo(leaky01(leaky01(dw.z)*m.z + mid_c.z));
    o.w = pack_hilo(leaky01(leaky01(dw.w)*m.w + mid_c.w));
    *(uint4*)&outp[((size_t)b*C_ + c)*HW_ + h*W_ + wq] = o;
}

// ---------------------------------------------------------------------------
// 3b) weight prep: fp32 OIHW -> bf16 hi/lo in m16n8k16 A-fragment order.
// ---------------------------------------------------------------------------
__global__ void wprep_kernel(const float* __restrict__ w1,
                             const float* __restrict__ w2)
{
    int idx = blockIdx.x * blockDim.x + threadIdx.x;
    if (idx >= 2*4*9*4*2*32*4) return;
    int t = idx;
    int r    = t & 3;  t >>= 2;
    int lane = t & 31; t >>= 5;
    int q    = t & 1;  t >>= 1;
    int mt   = t & 3;  t >>= 2;
    int s9   = t % 9;  t /= 9;
    int chunk= t & 3;  t >>= 2;
    int s2   = t;

    int g = lane >> 2, tig = lane & 3;
    int co = mt*16 + g + (r & 1)*8;
    int k0 = s9*16 + 2*tig + (r >> 1)*8;
    int k1 = k0 + 1;

    const float* w = s2 ? w2 : w1;
    int ci0 = k0/9, tap0 = k0 - ci0*9;
    int ci1 = k1/9, tap1 = k1 - ci1*9;
    float w0 = w[(co*C_ + chunk*16 + ci0)*9 + tap0];
    float w1v= w[(co*C_ + chunk*16 + ci1)*9 + tap1];

    u16 p0, p1;
    if (q == 0) {
        __nv_bfloat16 h0 = __float2bfloat16(w0), h1 = __float2bfloat16(w1v);
        p0 = *reinterpret_cast<u16*>(&h0); p1 = *reinterpret_cast<u16*>(&h1);
    } else {
        __nv_bfloat16 h0 = __float2bfloat16(w0);
        __nv_bfloat16 l0 = __float2bfloat16(w0 - __bfloat162float(h0));
        __nv_bfloat16 h1 = __float2bfloat16(w1v);
        __nv_bfloat16 l1 = __float2bfloat16(w1v - __bfloat162float(h1));
        p0 = *reinterpret_cast<u16*>(&l0); p1 = *reinterpret_cast<u16*>(&l1);
    }
    g_wA[idx] = ((u32)p1 << 16) | (u32)p0;
}

// ---------------------------------------------------------------------------
// 4) mma.sync conv v2: block = 2 rows (h0, h0+1), 256 threads = 8 warps.
//    Warp-group wg = wid>>2 handles row h0+wg; warp (wid&3) covers 32 px.
//    Double-buffered cp.async staging of weights (9216 u32/chunk) and
//    input (16 ci x 4 rows x RW2, packed u32, j = w+4 halo layout).
// ---------------------------------------------------------------------------
#define RW2  136
#define WCH  9216                       // u32 per weight chunk
#define ICH  (16*4*RW2)                 // 8704 u32 per input chunk
#define SMEM_DYN ((2*WCH + 2*ICH) * 4)  // 143360 B

__global__ void __launch_bounds__(256, 1)
conv_mma(const u32* __restrict__ pin,
         const u32* __restrict__ wA,
         const float* __restrict__ bias,
         const float* __restrict__ residual,
         float* __restrict__ out,
         int apply_leaky)
{
    extern __shared__ u32 dsm[];
    u32* wS[2] = { dsm, dsm + WCH };
    u32* iS[2] = { dsm + 2*WCH, dsm + 2*WCH + ICH };

    int tid = threadIdx.x;
    int wid = tid >> 5;
    int lane = tid & 31;
    int g = lane >> 2, tig = lane & 3;
    int wg = wid >> 2;                   // row group 0/1
    int warpbase = (wid & 3) * 32;
    int h0 = blockIdx.x * 2, b = blockIdx.z;
    int h = h0 + wg;

    // zero input buffers once (halo cols j<4, j>=132 and off-image rows stay 0)
    for (int i = tid; i < 2*ICH; i += 256) dsm[2*WCH + i] = 0;

    u32 wS_a[2] = { smem_u32(wS[0]), smem_u32(wS[1]) };
    u32 iS_a[2] = { smem_u32(iS[0]), smem_u32(iS[1]) };
    __syncthreads();

    // prefetch chunk into buffer buf
    auto prefetch = [&](int chunk, int buf) {
        // weights: 2304 x 16B
        const u32* wsrc = wA + chunk * WCH;
#pragma unroll
        for (int i = 0; i < 9; i++) {
            int idx = tid + i*256;                 // 0..2303
            cp_async16(wS_a[buf] + (u32)(idx*16), wsrc + idx*4);
        }
        // input: 16 ci x 4 rows x 32 segs = 2048 x 16B
#pragma unroll
        for (int i = 0; i < 8; i++) {
            int idx = tid + i*256;
            int ci  = idx >> 7;
            int rr  = (idx >> 5) & 3;
            int seg = idx & 31;
            int gy  = h0 - 1 + rr;
            if (gy >= 0 && gy < H_) {
                u32 dst = iS_a[buf] + (u32)(((ci*4 + rr)*RW2 + 4 + seg*4) * 4);
                cp_async16(dst, pin + (((size_t)b*C_ + chunk*16 + ci)*H_ + gy)*W_ + seg*4);
            }
        }
    };

    float D[4][4][4];
#pragma unroll
    for (int mt = 0; mt < 4; mt++)
#pragma unroll
        for (int nt = 0; nt < 4; nt++)
#pragma unroll
            for (int i = 0; i < 4; i++) D[mt][nt][i] = 0.f;

    prefetch(0, 0);
    cp_commit();

    for (int chunk = 0; chunk < 4; chunk++) {
        cp_wait_all();
        __syncthreads();                 // buffer chunk&1 ready for all warps

        if (chunk < 3) {
            prefetch(chunk + 1, (chunk + 1) & 1);
            cp_commit();
        }

        const u32* smW = wS[chunk & 1];
        const u32* inS = iS[chunk & 1];

#pragma unroll
        for (int s = 0; s < 9; s++) {
            uint4 Ah[4], Al[4];
#pragma unroll
            for (int mt = 0; mt < 4; mt++) {
                const u32* base = smW + ((s*4 + mt)*2)*128 + lane*4;
                Ah[mt] = *(const uint4*)(base);
                Al[mt] = *(const uint4*)(base + 128);
            }
#pragma unroll
            for (int nt = 0; nt < 4; nt++) {
                int n = warpbase + nt*8 + g;     // pixel
                u32 bh[2], bl[2];
#pragma unroll
                for (int r = 0; r < 2; r++) {
                    int k0 = s*16 + 2*tig + r*8;
                    int k1 = k0 + 1;
                    int ci0 = k0/9, tap0 = k0 - ci0*9;
                    int ci1 = k1/9, tap1 = k1 - ci1*9;
                    // j = px + tapc + 3 ; row = ci*4 + wg + tapr
                    u32 v0 = inS[(ci0*4 + wg + tap0/3)*RW2 + n + (tap0 % 3) + 3];
                    u32 v1 = inS[(ci1*4 + wg + tap1/3)*RW2 + n + (tap1 % 3) + 3];
                    bh[r] = __byte_perm(v0, v1, 0x7632);
                    bl[r] = __byte_perm(v0, v1, 0x5410);
                }
#pragma unroll
                for (int mt = 0; mt < 4; mt++) {
                    mma16816(D[mt][nt], (const u32*)&Ah[mt], bh[0], bh[1]);
                    mma16816(D[mt][nt], (const u32*)&Ah[mt], bl[0], bl[1]);
                    mma16816(D[mt][nt], (const u32*)&Al[mt], bh[0], bh[1]);
                }
            }
        }
        // no trailing sync needed: next iteration's wait+sync precedes any
        // prefetch that would overwrite this buffer
    }

    // ---- epilogue ----
#pragma unroll
    for (int mt = 0; mt < 4; mt++) {
        int co0 = mt*16 + g;
        float bv0 = bias[co0], bv1 = bias[co0 + 8];
#pragma unroll
        for (int nt = 0; nt < 4; nt++) {
            int px = warpbase + nt*8 + 2*tig;
            size_t o0 = (((size_t)b*C_ + co0    )*H_ + h)*W_ + px;
            size_t o1 = (((size_t)b*C_ + co0 + 8)*H_ + h)*W_ + px;
            float2 v0 = make_float2(D[mt][nt][0] + bv0, D[mt][nt][1] + bv0);
            float2 v1 = make_float2(D[mt][nt][2] + bv1, D[mt][nt][3] + bv1);
            if (apply_leaky) {
                v0.x = leaky01(v0.x); v0.y = leaky01(v0.y);
                v1.x = leaky01(v1.x); v1.y = leaky01(v1.y);
            }
            if (residual) {
                const float2 r0 = *(const float2*)&residual[o0];
                const float2 r1 = *(const float2*)&residual[o1];
                v0.x += r0.x; v0.y += r0.y; v1.x += r1.x; v1.y += r1.y;
            }
            *(float2*)&out[o0] = v0;
            *(float2*)&out[o1] = v1;
        }
    }
}

// ---------------------------------------------------------------------------
// launch
// ---------------------------------------------------------------------------
extern "C" void kernel_launch(void* const* d_in, const int* in_sizes, int n_in,
                              void* d_out, int out_size)
{
    const float* x       = (const float*)d_in[0];
    const float* d       = (const float*)d_in[1];
    const float* da1_k1  = (const float*)d_in[2];
    const float* da1_k2  = (const float*)d_in[3];
    const float* da1_cw  = (const float*)d_in[4];
    const float* da1_cb  = (const float*)d_in[5];
    const float* da2_k1  = (const float*)d_in[6];
    const float* da2_k2  = (const float*)d_in[7];
    const float* da2_cw  = (const float*)d_in[8];
    const float* da2_cb  = (const float*)d_in[9];
    const float* conv1_w = (const float*)d_in[10];
    const float* conv1_b = (const float*)d_in[11];
    const float* conv2_w = (const float*)d_in[12];
    const float* conv2_b = (const float*)d_in[13];
    float* out = (float*)d_out;

    u32 *buf1, *wa; float *buf2, *gate, *kern1, *kern2;
    cudaGetSymbolAddress((void**)&buf1,  g_buf1);
    cudaGetSymbolAddress((void**)&buf2,  g_buf2);
    cudaGetSymbolAddress((void**)&gate,  g_gate);
    cudaGetSymbolAddress((void**)&kern1, g_kern1);
    cudaGetSymbolAddress((void**)&kern2, g_kern2);
    cudaGetSymbolAddress((void**)&wa,    g_wA);

    cudaFuncSetAttribute(conv_mma, cudaFuncAttributeMaxDynamicSharedMemorySize, SMEM_DYN);

    mlp_kernel<<<dim3(B_, 2), 64>>>(d, da1_k1, da1_k2, da2_k1, da2_k2, kern1, kern2);
    wprep_kernel<<<(2*4*9*4*2*32*4 + 255)/256, 256>>>(conv1_w, conv2_w);

    gate_kernel<<<(B_*HW_/4)/256, 256>>>(x, da1_cw, da1_cb, gate);
    rda_kernel<<<dim3(HW_/4/256, C_, B_), 256>>>(x, kern1, gate, buf1);

    conv_mma<<<dim3(H_/2, 1, B_), 256, SMEM_DYN>>>(buf1, wa, conv1_b, nullptr, buf2, 1);

    gate_kernel<<<(B_*HW_/4)/256, 256>>>(buf2, da2_cw, da2_cb, gate);
    rda_kernel<<<dim3(HW_/4/256, C_, B_), 256>>>(buf2, kern2, gate, buf1);

    conv_mma<<<dim3(H_/2, 1, B_), 256, SMEM_DYN>>>(buf1, wa + 4*WCH,
                                                   conv2_b, x, out, 0);
}